// round 13
// baseline (speedup 1.0000x reference)
#include <cuda_runtime.h>
#include <cuda_bf16.h>
#include <math.h>
#include <stdint.h>

// ---------------------------------------------------------------------------
// Problem constants
// ---------------------------------------------------------------------------
#define B        8
#define CIN      15          // 3*5 after reshape
#define C1       64
#define H0       512
#define W0       512
#define H1       256
#define W1       256
#define C2       128
#define H2       128
#define W2       128
#define NE       3
#define CONV1_K  (CIN*7*7)   // 735
#define CONV2_K  (C1*3*3)    // 576

// Deinterleaved padded input: per row [even 260 | odd 260] floats, 520 rows.
#define XW  520
#define XR  520
// ebuf1 (conv1 out, 256x256) deinterleaved: row = iy+1 (258 rows),
// [even 128 | odd 132] = 260 floats
#define E1R 258
#define E1W 260
// NHWC padded activation for head1 (conv2 out): [B][130][132][128] bf16 x2
#define AR 130
#define AW 132

// ---------------------------------------------------------------------------
// Device scratch
// ---------------------------------------------------------------------------
__device__ __align__(16) float d_xpad  [(long)B*CIN*XR*XW];
__device__ __align__(16) float d_gbuf  [(long)B*C1*H1*W1];
__device__ __align__(16) float d_ebuf1p[(long)B*C1*E1R*E1W];
__device__ __align__(16) __nv_bfloat16 d_act_hi[(long)B*AR*AW*C2];
__device__ __align__(16) __nv_bfloat16 d_act_lo[(long)B*AR*AW*C2];
__device__ __align__(16) __nv_bfloat16 d_w1h[NE*9*C2*C2];
__device__ __align__(16) __nv_bfloat16 d_w1l[NE*9*C2*C2];
__device__ __align__(16) float d_ebuf3 [(long)B*C2*H2*W2];
__device__ float d_pooled[B*C1];
__device__ int   d_eidx[B];

// ---------------------------------------------------------------------------
// Packed f32x2 helpers
// ---------------------------------------------------------------------------
__device__ __forceinline__ unsigned long long pack2(float v) {
    unsigned long long r;
    asm("mov.b64 %0, {%1, %1};" : "=l"(r) : "f"(v));
    return r;
}
__device__ __forceinline__ void ffma2(unsigned long long& d,
                                      unsigned long long a,
                                      unsigned long long b) {
    asm("fma.rn.f32x2 %0, %1, %2, %0;" : "+l"(d) : "l"(a), "l"(b));
}
__device__ __forceinline__ float f2lo(unsigned long long v) {
    return __uint_as_float((unsigned int)v);
}
__device__ __forceinline__ float f2hi(unsigned long long v) {
    return __uint_as_float((unsigned int)(v >> 32));
}

#define FFMA2_8(accp, vv, wA, wB) do {                                \
    ffma2((accp)[0], (vv), (wA).x); ffma2((accp)[1], (vv), (wA).y);   \
    ffma2((accp)[2], (vv), (wB).x); ffma2((accp)[3], (vv), (wB).y);   \
} while (0)

// ---------------------------------------------------------------------------
// Warp-level bf16 MMA (baseline PTX ISA — compiles for compute_103)
// D(16x8,f32) += A(16x16,bf16 row-major) * B(16x8,bf16 col-major)
// ---------------------------------------------------------------------------
__device__ __forceinline__ void mma_bf16(float* d,
                                         uint32_t a0, uint32_t a1,
                                         uint32_t a2, uint32_t a3,
                                         uint32_t b0, uint32_t b1)
{
    asm volatile(
        "mma.sync.aligned.m16n8k16.row.col.f32.bf16.bf16.f32 "
        "{%0,%1,%2,%3}, {%4,%5,%6,%7}, {%8,%9}, {%0,%1,%2,%3};"
        : "+f"(d[0]), "+f"(d[1]), "+f"(d[2]), "+f"(d[3])
        : "r"(a0), "r"(a1), "r"(a2), "r"(a3), "r"(b0), "r"(b1));
}

__device__ __forceinline__ uint32_t ld32(const void* p) {
    return *(const uint32_t*)p;
}

// ---------------------------------------------------------------------------
// Kernel 0: prep — pad/deinterleave input, ebuf1 halos, NHWC halos, weight split
// ---------------------------------------------------------------------------
#define PREP_X    (B*CIN*XR)
#define PREP_E1   (PREP_X + B*C1)
#define PREP_ACT  (PREP_E1 + B)
#define PREP_W    (PREP_ACT + NE*9)

__global__ void __launch_bounds__(256)
prep_kernel(const float* __restrict__ x, const float* __restrict__ e_hw1)
{
    const int blk = blockIdx.x;
    const int t   = threadIdx.x;
    if (blk < PREP_X) {
        const int bc = blk / XR;
        const int r  = blk - bc * XR;
        const int iy = r - 3;
        float* dst = d_xpad + (long)blk * XW;
        const bool rowok = (unsigned)iy < (unsigned)H0;
        if (!rowok) {
            for (int c = t; c < XW; c += 256) dst[c] = 0.f;
        } else {
            const float* src = x + (long)bc * (H0 * W0) + (long)iy * W0;
            if (t < 128) {
                const float4 v = *(const float4*)(src + 4 * t);
                dst[1 + 2 * t]       = v.x;
                dst[2 + 2 * t]       = v.z;
                dst[260 + 2 + 2 * t] = v.y;
                dst[260 + 3 + 2 * t] = v.w;
            } else if (t == 128) {
                dst[0] = 0.f; dst[257] = 0.f; dst[258] = 0.f; dst[259] = 0.f;
                dst[260] = 0.f; dst[261] = 0.f; dst[518] = 0.f; dst[519] = 0.f;
            }
        }
    } else if (blk < PREP_E1) {
        float* p = d_ebuf1p + (long)(blk - PREP_X) * (E1R * E1W);
        for (int i = t; i < E1W; i += 256) p[i] = 0.f;      // row 0
        {
            float* r = p + (t + 1) * E1W;                   // rows 1..256
            r[128] = 0.f;
            r[257] = 0.f; r[258] = 0.f; r[259] = 0.f;
        }
    } else if (blk < PREP_ACT) {
        // NHWC activation halos: rows 0 & 129 full; cols 0 & 129 of rows 1..128
        const int bb = blk - PREP_E1;
        const uint4 z = make_uint4(0, 0, 0, 0);
        for (int pl = 0; pl < 2; pl++) {
            __nv_bfloat16* A = pl ? d_act_lo : d_act_hi;
            uint4* r0 = (uint4*)(A + ((long)bb * AR + 0) * AW * C2);
            uint4* r1 = (uint4*)(A + ((long)bb * AR + 129) * AW * C2);
            for (int i = t; i < AW * C2 / 8; i += 256) { r0[i] = z; r1[i] = z; }
            for (int i = t; i < 128 * 2 * 16; i += 256) {
                const int py  = 1 + (i >> 5);
                const int rem = i & 31;
                const int px  = (rem & 16) ? 129 : 0;
                const int ch  = rem & 15;
                *((uint4*)(A + (((long)bb * AR + py) * AW + px) * C2) + ch) = z;
            }
        }
    } else {
        // weight split: d_w1{h,l}[e][s][oc][ic]
        const int ws = blk - PREP_ACT;         // 0..26
        const int e  = ws / 9;
        const int s  = ws - e * 9;
        __nv_bfloat16* WH = d_w1h + (long)ws * (C2 * C2);
        __nv_bfloat16* WL = d_w1l + (long)ws * (C2 * C2);
        for (int i = t; i < C2 * C2; i += 256) {
            const int oc = i >> 7, ic = i & 127;
            const float w = e_hw1[(((long)e * C2 + oc) * C2 + ic) * 9 + s];
            const __nv_bfloat16 h = __float2bfloat16(w);
            WH[i] = h;
            WL[i] = __float2bfloat16(w - __bfloat162float(h));
        }
    }
}

// ---------------------------------------------------------------------------
// Kernel 1: 7x7 s2 conv, 15 -> 64  (R10 form, proven)
// ---------------------------------------------------------------------------
template <bool GATING>
__global__ void __launch_bounds__(128, 4)
conv7x7_kernel(const float* __restrict__ w_all,
               const float* __restrict__ bn_gamma,
               const float* __restrict__ bn_beta,
               const float* __restrict__ bn_mean,
               const float* __restrict__ bn_var)
{
    const int oy  = blockIdx.x * 4 + (threadIdx.x >> 5);
    const int ocg = blockIdx.y;
    const int b   = blockIdx.z;
    const int l   = threadIdx.x & 31;

    const float* w = w_all + (long)ocg * 8 * CONV1_K;
    if (!GATING) w += (long)d_eidx[b] * (C1 * CONV1_K);

    __shared__ __align__(16) float wsm[CONV1_K][8];
    for (int idx = threadIdx.x; idx < 8 * CONV1_K; idx += 128) {
        const int o = idx / CONV1_K;
        const int k = idx - o * CONV1_K;
        wsm[k][o] = w[idx];
    }
    __syncthreads();

    unsigned long long acc[8][4];
#pragma unroll
    for (int p = 0; p < 8; p++)
#pragma unroll
        for (int j = 0; j < 4; j++) acc[p][j] = 0ull;

    const float* xb = d_xpad + (long)b * CIN * (XR * XW);
#pragma unroll 1
    for (int ic = 0; ic < CIN; ic++) {
#pragma unroll 1
        for (int ky = 0; ky < 7; ky++) {
            const float* row = xb + ((long)ic * XR + (2 * oy + ky)) * XW;
            const float4 e0 = *(const float4*)(row + 8 * l);
            const float4 e1 = *(const float4*)(row + 8 * l + 4);
            const float4 e2 = *(const float4*)(row + 8 * l + 8);
            const float4 q0 = *(const float4*)(row + 260 + 8 * l);
            const float4 q1 = *(const float4*)(row + 260 + 8 * l + 4);
            const float4 q2 = *(const float4*)(row + 260 + 8 * l + 8);
            const float E[12] = {e0.x, e0.y, e0.z, e0.w, e1.x, e1.y, e1.z, e1.w,
                                 e2.x, e2.y, e2.z, e2.w};
            const float O[12] = {q0.x, q0.y, q0.z, q0.w, q1.x, q1.y, q1.z, q1.w,
                                 q2.x, q2.y, q2.z, q2.w};
            const int kb = (ic * 7 + ky) * 7;
#pragma unroll
            for (int kx = 0; kx < 7; kx++) {
                const ulonglong2* wp = (const ulonglong2*)wsm[kb + kx];
                const ulonglong2 wA = wp[0], wB = wp[1];
#pragma unroll
                for (int p = 0; p < 8; p++) {
                    const float v = (kx & 1) ? E[p + ((kx - 1) >> 1)]
                                             : O[p + (kx >> 1)];
                    const unsigned long long vv = pack2(v);
                    FFMA2_8(acc[p], vv, wA, wB);
                }
            }
        }
    }

    if (GATING) {
#pragma unroll
        for (int j = 0; j < 4; j++) {
            const int oca = ocg * 8 + 2 * j;
            const int ocb = oca + 1;
            const float sa = bn_gamma[oca] * rsqrtf(bn_var[oca] + 1e-5f);
            const float sb = bn_gamma[ocb] * rsqrtf(bn_var[ocb] + 1e-5f);
            const float ta = bn_beta[oca] - bn_mean[oca] * sa;
            const float tb = bn_beta[ocb] - bn_mean[ocb] * sb;
            float4 va0, va1, vb0, vb1;
            va0.x = fmaxf(f2lo(acc[0][j]) * sa + ta, 0.f);
            va0.y = fmaxf(f2lo(acc[1][j]) * sa + ta, 0.f);
            va0.z = fmaxf(f2lo(acc[2][j]) * sa + ta, 0.f);
            va0.w = fmaxf(f2lo(acc[3][j]) * sa + ta, 0.f);
            va1.x = fmaxf(f2lo(acc[4][j]) * sa + ta, 0.f);
            va1.y = fmaxf(f2lo(acc[5][j]) * sa + ta, 0.f);
            va1.z = fmaxf(f2lo(acc[6][j]) * sa + ta, 0.f);
            va1.w = fmaxf(f2lo(acc[7][j]) * sa + ta, 0.f);
            vb0.x = fmaxf(f2hi(acc[0][j]) * sb + tb, 0.f);
            vb0.y = fmaxf(f2hi(acc[1][j]) * sb + tb, 0.f);
            vb0.z = fmaxf(f2hi(acc[2][j]) * sb + tb, 0.f);
            vb0.w = fmaxf(f2hi(acc[3][j]) * sb + tb, 0.f);
            vb1.x = fmaxf(f2hi(acc[4][j]) * sb + tb, 0.f);
            vb1.y = fmaxf(f2hi(acc[5][j]) * sb + tb, 0.f);
            vb1.z = fmaxf(f2hi(acc[6][j]) * sb + tb, 0.f);
            vb1.w = fmaxf(f2hi(acc[7][j]) * sb + tb, 0.f);
            float* pa = d_gbuf + ((long)(b * C1 + oca) * H1 + oy) * W1 + 8 * l;
            float* pb = d_gbuf + ((long)(b * C1 + ocb) * H1 + oy) * W1 + 8 * l;
            *(float4*)(pa)     = va0;  *(float4*)(pa + 4) = va1;
            *(float4*)(pb)     = vb0;  *(float4*)(pb + 4) = vb1;
        }
    } else {
#pragma unroll
        for (int j = 0; j < 4; j++) {
            const int oca = ocg * 8 + 2 * j;
            const int ocb = oca + 1;
            float* ra = d_ebuf1p + ((long)(b * C1 + oca) * E1R + (oy + 1)) * E1W;
            float* rb = d_ebuf1p + ((long)(b * C1 + ocb) * E1R + (oy + 1)) * E1W;
            float4 ea, eb;
            ea.x = fmaxf(f2lo(acc[0][j]), 0.f);
            ea.y = fmaxf(f2lo(acc[2][j]), 0.f);
            ea.z = fmaxf(f2lo(acc[4][j]), 0.f);
            ea.w = fmaxf(f2lo(acc[6][j]), 0.f);
            eb.x = fmaxf(f2hi(acc[0][j]), 0.f);
            eb.y = fmaxf(f2hi(acc[2][j]), 0.f);
            eb.z = fmaxf(f2hi(acc[4][j]), 0.f);
            eb.w = fmaxf(f2hi(acc[6][j]), 0.f);
            *(float4*)(ra + 4 * l) = ea;
            *(float4*)(rb + 4 * l) = eb;
            ra[129 + 4 * l] = fmaxf(f2lo(acc[1][j]), 0.f);
            ra[130 + 4 * l] = fmaxf(f2lo(acc[3][j]), 0.f);
            ra[131 + 4 * l] = fmaxf(f2lo(acc[5][j]), 0.f);
            ra[132 + 4 * l] = fmaxf(f2lo(acc[7][j]), 0.f);
            rb[129 + 4 * l] = fmaxf(f2hi(acc[1][j]), 0.f);
            rb[130 + 4 * l] = fmaxf(f2hi(acc[3][j]), 0.f);
            rb[131 + 4 * l] = fmaxf(f2hi(acc[5][j]), 0.f);
            rb[132 + 4 * l] = fmaxf(f2hi(acc[7][j]), 0.f);
        }
    }
}

// ---------------------------------------------------------------------------
// Kernel 2: maxpool 3x3 s2 pad1 + spatial mean, per (b,c).
// ---------------------------------------------------------------------------
__global__ void pool_mean_kernel()
{
    const int bc = blockIdx.x;
    const float* p = d_gbuf + (long)bc * (H1 * W1);
    float sum = 0.f;
    for (int i = threadIdx.x; i < H2 * W2; i += blockDim.x) {
        const int py = i >> 7, px = i & 127;
        float m = -1e30f;
#pragma unroll
        for (int dy = 0; dy < 3; dy++) {
            const int iy = py * 2 - 1 + dy;
            if ((unsigned)iy >= (unsigned)H1) continue;
            const float* row = p + iy * W1;
#pragma unroll
            for (int dx = 0; dx < 3; dx++) {
                const int ix = px * 2 - 1 + dx;
                if ((unsigned)ix < (unsigned)W1) m = fmaxf(m, row[ix]);
            }
        }
        sum += m;
    }
    __shared__ float red[256];
    red[threadIdx.x] = sum;
    __syncthreads();
    for (int s = 128; s > 0; s >>= 1) {
        if (threadIdx.x < s) red[threadIdx.x] += red[threadIdx.x + s];
        __syncthreads();
    }
    if (threadIdx.x == 0) d_pooled[bc] = red[0] * (1.f / (H2 * W2));
}

// ---------------------------------------------------------------------------
// Kernel 3: FC -> logits -> top-1 expert + aux loss.
// ---------------------------------------------------------------------------
__global__ void gate_finalize_kernel(const float* __restrict__ fcw,
                                     const float* __restrict__ fcb,
                                     float* __restrict__ out_loss)
{
    __shared__ float logits[B][NE];
    const int t = threadIdx.x;
    if (t < B * NE) {
        const int b = t / NE, e = t % NE;
        float s = fcb[e];
        const float* pw = fcw + e * C1;
        const float* pp = d_pooled + b * C1;
        for (int i = 0; i < C1; i++) s += pp[i] * pw[i];
        logits[b][e] = s;
    }
    __syncthreads();
    if (t == 0) {
        float dens[NE]  = {0.f, 0.f, 0.f};
        float proxy[NE] = {0.f, 0.f, 0.f};
        for (int b = 0; b < B; b++) {
            int bi = 0;
            for (int e = 1; e < NE; e++)
                if (logits[b][e] > logits[b][bi]) bi = e;
            d_eidx[b] = bi;
            dens[bi] += 1.f / B;
            float mx = logits[b][0];
            for (int e = 1; e < NE; e++) mx = fmaxf(mx, logits[b][e]);
            float ex[NE], sum = 0.f;
            for (int e = 0; e < NE; e++) { ex[e] = expf(logits[b][e] - mx); sum += ex[e]; }
            for (int e = 0; e < NE; e++) proxy[e] += ex[e] / sum * (1.f / B);
        }
        float aux = 0.f;
        for (int e = 0; e < NE; e++) aux += dens[e] * proxy[e];
        *out_loss = 0.01f * aux * (float)NE;
    }
}

// ---------------------------------------------------------------------------
// Kernel 4: 3x3 s2 conv, 64 -> 128.  Epilogue writes NHWC bf16x2.
// Block 128 thr = 8 output rows x 16 lanes; lane computes 8 px, 8 oc.
// Grid (16, 16, 8).
// ---------------------------------------------------------------------------
__global__ void __launch_bounds__(128, 4)
conv2_kernel(const float* __restrict__ w_all)
{
    const int oy  = blockIdx.x * 8 + (threadIdx.x >> 4);
    const int ocg = blockIdx.y;
    const int b   = blockIdx.z;
    const int l   = threadIdx.x & 15;

    const float* w = w_all + ((long)d_eidx[b] * C2 + ocg * 8) * CONV2_K;
    __shared__ __align__(16) float wsm[CONV2_K][8];
    for (int idx = threadIdx.x; idx < 8 * CONV2_K; idx += 128) {
        const int o = idx / CONV2_K;
        const int k = idx - o * CONV2_K;
        wsm[k][o] = w[idx];
    }
    __syncthreads();

    unsigned long long acc[8][4];
#pragma unroll
    for (int p = 0; p < 8; p++)
#pragma unroll
        for (int j = 0; j < 4; j++) acc[p][j] = 0ull;

    const float* ib = d_ebuf1p + (long)b * C1 * (E1R * E1W);
#pragma unroll 1
    for (int ic = 0; ic < C1; ic++) {
        const float* xc = ib + (long)ic * (E1R * E1W);
#pragma unroll
        for (int ky = 0; ky < 3; ky++) {
            const float* row = xc + (2 * oy + ky) * E1W;
            const float4 e0 = *(const float4*)(row + 8 * l);
            const float4 e1 = *(const float4*)(row + 8 * l + 4);
            const float4 q0 = *(const float4*)(row + 128 + 8 * l);
            const float4 q1 = *(const float4*)(row + 128 + 8 * l + 4);
            const float4 q2 = *(const float4*)(row + 128 + 8 * l + 8);
            const float E[8]  = {e0.x, e0.y, e0.z, e0.w, e1.x, e1.y, e1.z, e1.w};
            const float O[12] = {q0.x, q0.y, q0.z, q0.w, q1.x, q1.y, q1.z, q1.w,
                                 q2.x, q2.y, q2.z, q2.w};
            const int kb = (ic * 3 + ky) * 3;
#pragma unroll
            for (int kx = 0; kx < 3; kx++) {
                const ulonglong2* wp = (const ulonglong2*)wsm[kb + kx];
                const ulonglong2 wA = wp[0], wB = wp[1];
#pragma unroll
                for (int p = 0; p < 8; p++) {
                    const float v = (kx == 1) ? E[p] : ((kx == 0) ? O[p] : O[p + 1]);
                    const unsigned long long vv = pack2(v);
                    FFMA2_8(acc[p], vv, wA, wB);
                }
            }
        }
    }

    // NHWC bf16x2 epilogue: [b][oy+1][px+1][oc], oc = ocg*8 + 0..7
#pragma unroll
    for (int p = 0; p < 8; p++) {
        __align__(16) __nv_bfloat16 hi8[8];
        __align__(16) __nv_bfloat16 lo8[8];
#pragma unroll
        for (int j = 0; j < 4; j++) {
            const float va = fmaxf(f2lo(acc[p][j]), 0.f);
            const float vb = fmaxf(f2hi(acc[p][j]), 0.f);
            const __nv_bfloat16 ha = __float2bfloat16(va);
            const __nv_bfloat16 hb = __float2bfloat16(vb);
            hi8[2 * j]     = ha;
            lo8[2 * j]     = __float2bfloat16(va - __bfloat162float(ha));
            hi8[2 * j + 1] = hb;
            lo8[2 * j + 1] = __float2bfloat16(vb - __bfloat162float(hb));
        }
        const long off = (((long)b * AR + (oy + 1)) * AW + (8 * l + p + 1)) * C2
                       + ocg * 8;
        *(uint4*)(d_act_hi + off) = *(const uint4*)hi8;
        *(uint4*)(d_act_lo + off) = *(const uint4*)lo8;
    }
}

// ---------------------------------------------------------------------------
// Kernel 5: head1 via warp-level mma.sync bf16x2 implicit GEMM.
// Grid (128 rows, 2 oc-halves, 8 batch), 128 threads = 4 warps.
// Warp computes 32 px x 64 oc; fragments loaded directly from global.
// 3 products (hi*hi + hi*lo + lo*hi) in fp32 accumulation.
// ---------------------------------------------------------------------------
__global__ void __launch_bounds__(128)
head1_mma_kernel(const float* __restrict__ b_all)
{
    const int oy   = blockIdx.x;
    const int h    = blockIdx.y;          // oc-half: 0 or 1
    const int b    = blockIdx.z;
    const int t    = threadIdx.x;
    const int wid  = t >> 5;
    const int lane = t & 31;
    const int g    = lane >> 2;           // groupID 0..7
    const int tg   = lane & 3;            // threadID_in_group 0..3
    const int e    = d_eidx[b];
    const int px0  = wid * 32;

    float acc[2][8][4];
#pragma unroll
    for (int mt = 0; mt < 2; mt++)
#pragma unroll
        for (int nt = 0; nt < 8; nt++)
#pragma unroll
            for (int j = 0; j < 4; j++) acc[mt][nt][j] = 0.f;

#pragma unroll 1
    for (int s = 0; s < 9; s++) {
        const int dy = s / 3, dx = s - 3 * dy;
        const __nv_bfloat16* ah = d_act_hi + (((long)b * AR + (oy + dy)) * AW + dx) * C2;
        const __nv_bfloat16* al = d_act_lo + (((long)b * AR + (oy + dy)) * AW + dx) * C2;
        const __nv_bfloat16* wh = d_w1h + (long)(e * 9 + s) * (C2 * C2) + (h * 64) * C2;
        const __nv_bfloat16* wl = d_w1l + (long)(e * 9 + s) * (C2 * C2) + (h * 64) * C2;

#pragma unroll 1
        for (int ks = 0; ks < 8; ks++) {
            const int k0 = ks * 16;
            uint32_t AH[2][4], AL[2][4];
#pragma unroll
            for (int mt = 0; mt < 2; mt++) {
                const __nv_bfloat16* p = ah + (long)(px0 + mt * 16 + g) * C2 + k0 + 2 * tg;
                const __nv_bfloat16* q = al + (long)(px0 + mt * 16 + g) * C2 + k0 + 2 * tg;
                AH[mt][0] = ld32(p);
                AH[mt][1] = ld32(p + 8 * C2);
                AH[mt][2] = ld32(p + 8);
                AH[mt][3] = ld32(p + 8 * C2 + 8);
                AL[mt][0] = ld32(q);
                AL[mt][1] = ld32(q + 8 * C2);
                AL[mt][2] = ld32(q + 8);
                AL[mt][3] = ld32(q + 8 * C2 + 8);
            }
#pragma unroll
            for (int nt = 0; nt < 8; nt++) {
                const __nv_bfloat16* p = wh + (long)(nt * 8 + g) * C2 + k0 + 2 * tg;
                const __nv_bfloat16* q = wl + (long)(nt * 8 + g) * C2 + k0 + 2 * tg;
                const uint32_t BH0 = ld32(p), BH1 = ld32(p + 8);
                const uint32_t BL0 = ld32(q), BL1 = ld32(q + 8);
#pragma unroll
                for (int mt = 0; mt < 2; mt++) {
                    mma_bf16(acc[mt][nt], AH[mt][0], AH[mt][1], AH[mt][2], AH[mt][3], BH0, BH1);
                    mma_bf16(acc[mt][nt], AH[mt][0], AH[mt][1], AH[mt][2], AH[mt][3], BL0, BL1);
                    mma_bf16(acc[mt][nt], AL[mt][0], AL[mt][1], AL[mt][2], AL[mt][3], BH0, BH1);
                }
            }
        }
    }

    // Epilogue: D frag (mt,nt): rows px0+mt*16+g (+8), cols 2*tg (+1) within nt*8
#pragma unroll
    for (int nt = 0; nt < 8; nt++) {
        const int oc0 = h * 64 + nt * 8 + 2 * tg;
        const float bias0 = b_all[e * C2 + oc0];
        const float bias1 = b_all[e * C2 + oc0 + 1];
        float* o0 = d_ebuf3 + ((long)(b * C2 + oc0) * H2 + oy) * W2;
        float* o1 = d_ebuf3 + ((long)(b * C2 + oc0 + 1) * H2 + oy) * W2;
#pragma unroll
        for (int mt = 0; mt < 2; mt++) {
            const int px = px0 + mt * 16 + g;
            o0[px]     = fmaxf(acc[mt][nt][0] + bias0, 0.f);
            o1[px]     = fmaxf(acc[mt][nt][1] + bias1, 0.f);
            o0[px + 8] = fmaxf(acc[mt][nt][2] + bias0, 0.f);
            o1[px + 8] = fmaxf(acc[mt][nt][3] + bias1, 0.f);
        }
    }
}

// ---------------------------------------------------------------------------
// Kernel 6: 1x1 conv 128 -> 5 + bias, scatter into (hm, wh, reg) layout.
// ---------------------------------------------------------------------------
__global__ void __launch_bounds__(128)
head2_kernel(const float* __restrict__ w_all,
             const float* __restrict__ b_all,
             float* __restrict__ out)
{
    const int oy = blockIdx.x;
    const int b  = blockIdx.y;
    const int ox = threadIdx.x;
    const int e  = d_eidx[b];

    __shared__ __align__(16) float ws[C2][8];
    for (int idx = threadIdx.x; idx < 5 * C2; idx += 128) {
        const int j = idx / C2, ic = idx - j * C2;
        ws[ic][j] = w_all[(long)e * 5 * C2 + idx];
    }
    __syncthreads();

    float acc[5] = {0.f, 0.f, 0.f, 0.f, 0.f};
    const float* ib = d_ebuf3 + (long)b * C2 * H2 * W2 + oy * W2 + ox;
    for (int ic = 0; ic < C2; ic++) {
        const float v = __ldg(ib + ic * (H2 * W2));
        const float4 w4 = *(const float4*)ws[ic];
        acc[0] += v * w4.x;
        acc[1] += v * w4.y;
        acc[2] += v * w4.z;
        acc[3] += v * w4.w;
        acc[4] += v * ws[ic][4];
    }

    const int p  = oy * W2 + ox;
    const int HW = H2 * W2;
    const float* bb = b_all + e * 5;
    out[b * HW + p]                        = acc[0] + bb[0];
    out[B * HW + (b * 2 + 0) * HW + p]     = acc[1] + bb[1];
    out[B * HW + (b * 2 + 1) * HW + p]     = acc[2] + bb[2];
    out[3 * B * HW + (b * 2 + 0) * HW + p] = acc[3] + bb[3];
    out[3 * B * HW + (b * 2 + 1) * HW + p] = acc[4] + bb[4];
}

// ---------------------------------------------------------------------------
// Launch
// ---------------------------------------------------------------------------
extern "C" void kernel_launch(void* const* d_in, const int* in_sizes, int n_in,
                              void* d_out, int out_size)
{
    const float* x        = (const float*)d_in[0];
    const float* g_conv_w = (const float*)d_in[1];
    const float* g_gamma  = (const float*)d_in[2];
    const float* g_beta   = (const float*)d_in[3];
    const float* g_mean   = (const float*)d_in[4];
    const float* g_var    = (const float*)d_in[5];
    const float* g_fc_w   = (const float*)d_in[6];
    const float* g_fc_b   = (const float*)d_in[7];
    const float* e_conv1  = (const float*)d_in[8];
    const float* e_conv2  = (const float*)d_in[9];
    const float* e_hw1    = (const float*)d_in[10];
    const float* e_hb1    = (const float*)d_in[11];
    const float* e_hw2    = (const float*)d_in[12];
    const float* e_hb2    = (const float*)d_in[13];
    float* out = (float*)d_out;

    // 0. Pad/deinterleave input + halos + head1 weight bf16x2 split
    prep_kernel<<<PREP_W, 256>>>(x, e_hw1);
    // 1. Gating conv (7x7 s2) + BN + ReLU
    conv7x7_kernel<true><<<dim3(64, 8, B), 128>>>(g_conv_w, g_gamma, g_beta, g_mean, g_var);
    // 2. Maxpool + global average
    pool_mean_kernel<<<B * C1, 256>>>();
    // 3. Logits, top-1 expert selection, aux loss
    gate_finalize_kernel<<<1, 32>>>(g_fc_w, g_fc_b, out + (out_size - 1));
    // 4. Selected expert conv1 (7x7 s2) + ReLU -> ebuf1p (deinterleaved)
    conv7x7_kernel<false><<<dim3(64, 8, B), 128>>>(e_conv1, nullptr, nullptr, nullptr, nullptr);
    // 5. Expert conv2 (3x3 s2) + ReLU -> NHWC bf16x2
    conv2_kernel<<<dim3(16, 16, B), 128>>>(e_conv2);
    // 6. Head conv1 via mma.sync bf16x2 implicit GEMM -> ebuf3
    head1_mma_kernel<<<dim3(H2, 2, B), 128>>>(e_hb1);
    // 7. Head conv2 (1x1) + bias, scattered to (hm, wh, reg)
    head2_kernel<<<dim3(128, B), 128>>>(e_hw2, e_hb2, out);
}

// round 14
// speedup vs baseline: 1.1967x; 1.1967x over previous
#include <cuda_runtime.h>
#include <cuda_bf16.h>
#include <math.h>
#include <stdint.h>

// ---------------------------------------------------------------------------
// Problem constants
// ---------------------------------------------------------------------------
#define B        8
#define CIN      15          // 3*5 after reshape
#define C1       64
#define H0       512
#define W0       512
#define H1       256
#define W1       256
#define C2       128
#define H2       128
#define W2       128
#define NE       3
#define CONV1_K  (CIN*7*7)   // 735
#define CONV2_K  (C1*3*3)    // 576

// Deinterleaved padded input: per row [even 260 | odd 260] floats, 520 rows.
#define XW  520
#define XR  520
// ebuf1 (conv1 out, 256x256) deinterleaved: row = iy+1 (258 rows),
// [even 128 | odd 132] = 260 floats
#define E1R 258
#define E1W 260
// NHWC padded activation for head1 (conv2 out): [B][130][132][128] bf16 x2
#define AR 130
#define AW 132

// ---------------------------------------------------------------------------
// Device scratch
// ---------------------------------------------------------------------------
__device__ __align__(16) float d_xpad  [(long)B*CIN*XR*XW];
__device__ __align__(16) float d_gbuf  [(long)B*C1*H1*W1];
__device__ __align__(16) float d_ebuf1p[(long)B*C1*E1R*E1W];
__device__ __align__(16) __nv_bfloat16 d_act_hi[(long)B*AR*AW*C2];
__device__ __align__(16) __nv_bfloat16 d_act_lo[(long)B*AR*AW*C2];
__device__ __align__(16) __nv_bfloat16 d_w1h[NE*9*C2*C2];
__device__ __align__(16) __nv_bfloat16 d_w1l[NE*9*C2*C2];
__device__ __align__(16) float d_ebuf3 [(long)B*C2*H2*W2];
__device__ float d_pooled[B*C1];
__device__ int   d_eidx[B];

// ---------------------------------------------------------------------------
// Packed f32x2 helpers
// ---------------------------------------------------------------------------
__device__ __forceinline__ unsigned long long pack2(float v) {
    unsigned long long r;
    asm("mov.b64 %0, {%1, %1};" : "=l"(r) : "f"(v));
    return r;
}
__device__ __forceinline__ void ffma2(unsigned long long& d,
                                      unsigned long long a,
                                      unsigned long long b) {
    asm("fma.rn.f32x2 %0, %1, %2, %0;" : "+l"(d) : "l"(a), "l"(b));
}
__device__ __forceinline__ float f2lo(unsigned long long v) {
    return __uint_as_float((unsigned int)v);
}
__device__ __forceinline__ float f2hi(unsigned long long v) {
    return __uint_as_float((unsigned int)(v >> 32));
}

#define FFMA2_8(accp, vv, wA, wB) do {                                \
    ffma2((accp)[0], (vv), (wA).x); ffma2((accp)[1], (vv), (wA).y);   \
    ffma2((accp)[2], (vv), (wB).x); ffma2((accp)[3], (vv), (wB).y);   \
} while (0)

// ---------------------------------------------------------------------------
// Warp-level bf16 MMA + ldmatrix (baseline PTX ISA — compiles for compute_103)
// ---------------------------------------------------------------------------
__device__ __forceinline__ void mma_bf16(float* d,
                                         uint32_t a0, uint32_t a1,
                                         uint32_t a2, uint32_t a3,
                                         uint32_t b0, uint32_t b1)
{
    asm volatile(
        "mma.sync.aligned.m16n8k16.row.col.f32.bf16.bf16.f32 "
        "{%0,%1,%2,%3}, {%4,%5,%6,%7}, {%8,%9}, {%0,%1,%2,%3};"
        : "+f"(d[0]), "+f"(d[1]), "+f"(d[2]), "+f"(d[3])
        : "r"(a0), "r"(a1), "r"(a2), "r"(a3), "r"(b0), "r"(b1));
}
__device__ __forceinline__ void ldm_x4(uint32_t* r, uint32_t addr)
{
    asm volatile("ldmatrix.sync.aligned.m8n8.x4.shared.b16 {%0,%1,%2,%3}, [%4];"
                 : "=r"(r[0]), "=r"(r[1]), "=r"(r[2]), "=r"(r[3]) : "r"(addr));
}
__device__ __forceinline__ void ldm_x2(uint32_t& r0, uint32_t& r1, uint32_t addr)
{
    asm volatile("ldmatrix.sync.aligned.m8n8.x2.shared.b16 {%0,%1}, [%2];"
                 : "=r"(r0), "=r"(r1) : "r"(addr));
}
__device__ __forceinline__ uint32_t smem_u32(const void* p) {
    uint32_t a;
    asm("{ .reg .u64 t; cvta.to.shared.u64 t, %1; cvt.u32.u64 %0, t; }"
        : "=r"(a) : "l"(p));
    return a;
}

// ---------------------------------------------------------------------------
// Kernel 0: prep — pad/deinterleave input, ebuf1 halos, NHWC halos, weight split
// ---------------------------------------------------------------------------
#define PREP_X    (B*CIN*XR)
#define PREP_E1   (PREP_X + B*C1)
#define PREP_ACT  (PREP_E1 + B)
#define PREP_W    (PREP_ACT + NE*9)

__global__ void __launch_bounds__(256)
prep_kernel(const float* __restrict__ x, const float* __restrict__ e_hw1)
{
    const int blk = blockIdx.x;
    const int t   = threadIdx.x;
    if (blk < PREP_X) {
        const int bc = blk / XR;
        const int r  = blk - bc * XR;
        const int iy = r - 3;
        float* dst = d_xpad + (long)blk * XW;
        const bool rowok = (unsigned)iy < (unsigned)H0;
        if (!rowok) {
            for (int c = t; c < XW; c += 256) dst[c] = 0.f;
        } else {
            const float* src = x + (long)bc * (H0 * W0) + (long)iy * W0;
            if (t < 128) {
                const float4 v = *(const float4*)(src + 4 * t);
                dst[1 + 2 * t]       = v.x;
                dst[2 + 2 * t]       = v.z;
                dst[260 + 2 + 2 * t] = v.y;
                dst[260 + 3 + 2 * t] = v.w;
            } else if (t == 128) {
                dst[0] = 0.f; dst[257] = 0.f; dst[258] = 0.f; dst[259] = 0.f;
                dst[260] = 0.f; dst[261] = 0.f; dst[518] = 0.f; dst[519] = 0.f;
            }
        }
    } else if (blk < PREP_E1) {
        float* p = d_ebuf1p + (long)(blk - PREP_X) * (E1R * E1W);
        for (int i = t; i < E1W; i += 256) p[i] = 0.f;      // row 0
        {
            float* r = p + (t + 1) * E1W;                   // rows 1..256
            r[128] = 0.f;
            r[257] = 0.f; r[258] = 0.f; r[259] = 0.f;
        }
    } else if (blk < PREP_ACT) {
        // NHWC activation halos: rows 0 & 129 full; cols 0 & 129 of rows 1..128
        const int bb = blk - PREP_E1;
        const uint4 z = make_uint4(0, 0, 0, 0);
        for (int pl = 0; pl < 2; pl++) {
            __nv_bfloat16* A = pl ? d_act_lo : d_act_hi;
            uint4* r0 = (uint4*)(A + ((long)bb * AR + 0) * AW * C2);
            uint4* r1 = (uint4*)(A + ((long)bb * AR + 129) * AW * C2);
            for (int i = t; i < AW * C2 / 8; i += 256) { r0[i] = z; r1[i] = z; }
            for (int i = t; i < 128 * 2 * 16; i += 256) {
                const int py  = 1 + (i >> 5);
                const int rem = i & 31;
                const int px  = (rem & 16) ? 129 : 0;
                const int ch  = rem & 15;
                *((uint4*)(A + (((long)bb * AR + py) * AW + px) * C2) + ch) = z;
            }
        }
    } else {
        // weight split: d_w1{h,l}[e][s][oc][ic]
        const int ws = blk - PREP_ACT;         // 0..26
        const int e  = ws / 9;
        const int s  = ws - e * 9;
        __nv_bfloat16* WH = d_w1h + (long)ws * (C2 * C2);
        __nv_bfloat16* WL = d_w1l + (long)ws * (C2 * C2);
        for (int i = t; i < C2 * C2; i += 256) {
            const int oc = i >> 7, ic = i & 127;
            const float w = e_hw1[(((long)e * C2 + oc) * C2 + ic) * 9 + s];
            const __nv_bfloat16 h = __float2bfloat16(w);
            WH[i] = h;
            WL[i] = __float2bfloat16(w - __bfloat162float(h));
        }
    }
}

// ---------------------------------------------------------------------------
// Kernel 1: 7x7 s2 conv, 15 -> 64  (R10 form, proven)
// ---------------------------------------------------------------------------
template <bool GATING>
__global__ void __launch_bounds__(128, 4)
conv7x7_kernel(const float* __restrict__ w_all,
               const float* __restrict__ bn_gamma,
               const float* __restrict__ bn_beta,
               const float* __restrict__ bn_mean,
               const float* __restrict__ bn_var)
{
    const int oy  = blockIdx.x * 4 + (threadIdx.x >> 5);
    const int ocg = blockIdx.y;
    const int b   = blockIdx.z;
    const int l   = threadIdx.x & 31;

    const float* w = w_all + (long)ocg * 8 * CONV1_K;
    if (!GATING) w += (long)d_eidx[b] * (C1 * CONV1_K);

    __shared__ __align__(16) float wsm[CONV1_K][8];
    for (int idx = threadIdx.x; idx < 8 * CONV1_K; idx += 128) {
        const int o = idx / CONV1_K;
        const int k = idx - o * CONV1_K;
        wsm[k][o] = w[idx];
    }
    __syncthreads();

    unsigned long long acc[8][4];
#pragma unroll
    for (int p = 0; p < 8; p++)
#pragma unroll
        for (int j = 0; j < 4; j++) acc[p][j] = 0ull;

    const float* xb = d_xpad + (long)b * CIN * (XR * XW);
#pragma unroll 1
    for (int ic = 0; ic < CIN; ic++) {
#pragma unroll 1
        for (int ky = 0; ky < 7; ky++) {
            const float* row = xb + ((long)ic * XR + (2 * oy + ky)) * XW;
            const float4 e0 = *(const float4*)(row + 8 * l);
            const float4 e1 = *(const float4*)(row + 8 * l + 4);
            const float4 e2 = *(const float4*)(row + 8 * l + 8);
            const float4 q0 = *(const float4*)(row + 260 + 8 * l);
            const float4 q1 = *(const float4*)(row + 260 + 8 * l + 4);
            const float4 q2 = *(const float4*)(row + 260 + 8 * l + 8);
            const float E[12] = {e0.x, e0.y, e0.z, e0.w, e1.x, e1.y, e1.z, e1.w,
                                 e2.x, e2.y, e2.z, e2.w};
            const float O[12] = {q0.x, q0.y, q0.z, q0.w, q1.x, q1.y, q1.z, q1.w,
                                 q2.x, q2.y, q2.z, q2.w};
            const int kb = (ic * 7 + ky) * 7;
#pragma unroll
            for (int kx = 0; kx < 7; kx++) {
                const ulonglong2* wp = (const ulonglong2*)wsm[kb + kx];
                const ulonglong2 wA = wp[0], wB = wp[1];
#pragma unroll
                for (int p = 0; p < 8; p++) {
                    const float v = (kx & 1) ? E[p + ((kx - 1) >> 1)]
                                             : O[p + (kx >> 1)];
                    const unsigned long long vv = pack2(v);
                    FFMA2_8(acc[p], vv, wA, wB);
                }
            }
        }
    }

    if (GATING) {
#pragma unroll
        for (int j = 0; j < 4; j++) {
            const int oca = ocg * 8 + 2 * j;
            const int ocb = oca + 1;
            const float sa = bn_gamma[oca] * rsqrtf(bn_var[oca] + 1e-5f);
            const float sb = bn_gamma[ocb] * rsqrtf(bn_var[ocb] + 1e-5f);
            const float ta = bn_beta[oca] - bn_mean[oca] * sa;
            const float tb = bn_beta[ocb] - bn_mean[ocb] * sb;
            float4 va0, va1, vb0, vb1;
            va0.x = fmaxf(f2lo(acc[0][j]) * sa + ta, 0.f);
            va0.y = fmaxf(f2lo(acc[1][j]) * sa + ta, 0.f);
            va0.z = fmaxf(f2lo(acc[2][j]) * sa + ta, 0.f);
            va0.w = fmaxf(f2lo(acc[3][j]) * sa + ta, 0.f);
            va1.x = fmaxf(f2lo(acc[4][j]) * sa + ta, 0.f);
            va1.y = fmaxf(f2lo(acc[5][j]) * sa + ta, 0.f);
            va1.z = fmaxf(f2lo(acc[6][j]) * sa + ta, 0.f);
            va1.w = fmaxf(f2lo(acc[7][j]) * sa + ta, 0.f);
            vb0.x = fmaxf(f2hi(acc[0][j]) * sb + tb, 0.f);
            vb0.y = fmaxf(f2hi(acc[1][j]) * sb + tb, 0.f);
            vb0.z = fmaxf(f2hi(acc[2][j]) * sb + tb, 0.f);
            vb0.w = fmaxf(f2hi(acc[3][j]) * sb + tb, 0.f);
            vb1.x = fmaxf(f2hi(acc[4][j]) * sb + tb, 0.f);
            vb1.y = fmaxf(f2hi(acc[5][j]) * sb + tb, 0.f);
            vb1.z = fmaxf(f2hi(acc[6][j]) * sb + tb, 0.f);
            vb1.w = fmaxf(f2hi(acc[7][j]) * sb + tb, 0.f);
            float* pa = d_gbuf + ((long)(b * C1 + oca) * H1 + oy) * W1 + 8 * l;
            float* pb = d_gbuf + ((long)(b * C1 + ocb) * H1 + oy) * W1 + 8 * l;
            *(float4*)(pa)     = va0;  *(float4*)(pa + 4) = va1;
            *(float4*)(pb)     = vb0;  *(float4*)(pb + 4) = vb1;
        }
    } else {
#pragma unroll
        for (int j = 0; j < 4; j++) {
            const int oca = ocg * 8 + 2 * j;
            const int ocb = oca + 1;
            float* ra = d_ebuf1p + ((long)(b * C1 + oca) * E1R + (oy + 1)) * E1W;
            float* rb = d_ebuf1p + ((long)(b * C1 + ocb) * E1R + (oy + 1)) * E1W;
            float4 ea, eb;
            ea.x = fmaxf(f2lo(acc[0][j]), 0.f);
            ea.y = fmaxf(f2lo(acc[2][j]), 0.f);
            ea.z = fmaxf(f2lo(acc[4][j]), 0.f);
            ea.w = fmaxf(f2lo(acc[6][j]), 0.f);
            eb.x = fmaxf(f2hi(acc[0][j]), 0.f);
            eb.y = fmaxf(f2hi(acc[2][j]), 0.f);
            eb.z = fmaxf(f2hi(acc[4][j]), 0.f);
            eb.w = fmaxf(f2hi(acc[6][j]), 0.f);
            *(float4*)(ra + 4 * l) = ea;
            *(float4*)(rb + 4 * l) = eb;
            ra[129 + 4 * l] = fmaxf(f2lo(acc[1][j]), 0.f);
            ra[130 + 4 * l] = fmaxf(f2lo(acc[3][j]), 0.f);
            ra[131 + 4 * l] = fmaxf(f2lo(acc[5][j]), 0.f);
            ra[132 + 4 * l] = fmaxf(f2lo(acc[7][j]), 0.f);
            rb[129 + 4 * l] = fmaxf(f2hi(acc[1][j]), 0.f);
            rb[130 + 4 * l] = fmaxf(f2hi(acc[3][j]), 0.f);
            rb[131 + 4 * l] = fmaxf(f2hi(acc[5][j]), 0.f);
            rb[132 + 4 * l] = fmaxf(f2hi(acc[7][j]), 0.f);
        }
    }
}

// ---------------------------------------------------------------------------
// Kernel 2: maxpool 3x3 s2 pad1 + spatial mean, per (b,c).
// ---------------------------------------------------------------------------
__global__ void pool_mean_kernel()
{
    const int bc = blockIdx.x;
    const float* p = d_gbuf + (long)bc * (H1 * W1);
    float sum = 0.f;
    for (int i = threadIdx.x; i < H2 * W2; i += blockDim.x) {
        const int py = i >> 7, px = i & 127;
        float m = -1e30f;
#pragma unroll
        for (int dy = 0; dy < 3; dy++) {
            const int iy = py * 2 - 1 + dy;
            if ((unsigned)iy >= (unsigned)H1) continue;
            const float* row = p + iy * W1;
#pragma unroll
            for (int dx = 0; dx < 3; dx++) {
                const int ix = px * 2 - 1 + dx;
                if ((unsigned)ix < (unsigned)W1) m = fmaxf(m, row[ix]);
            }
        }
        sum += m;
    }
    __shared__ float red[256];
    red[threadIdx.x] = sum;
    __syncthreads();
    for (int s = 128; s > 0; s >>= 1) {
        if (threadIdx.x < s) red[threadIdx.x] += red[threadIdx.x + s];
        __syncthreads();
    }
    if (threadIdx.x == 0) d_pooled[bc] = red[0] * (1.f / (H2 * W2));
}

// ---------------------------------------------------------------------------
// Kernel 3: FC -> logits -> top-1 expert + aux loss.
// ---------------------------------------------------------------------------
__global__ void gate_finalize_kernel(const float* __restrict__ fcw,
                                     const float* __restrict__ fcb,
                                     float* __restrict__ out_loss)
{
    __shared__ float logits[B][NE];
    const int t = threadIdx.x;
    if (t < B * NE) {
        const int b = t / NE, e = t % NE;
        float s = fcb[e];
        const float* pw = fcw + e * C1;
        const float* pp = d_pooled + b * C1;
        for (int i = 0; i < C1; i++) s += pp[i] * pw[i];
        logits[b][e] = s;
    }
    __syncthreads();
    if (t == 0) {
        float dens[NE]  = {0.f, 0.f, 0.f};
        float proxy[NE] = {0.f, 0.f, 0.f};
        for (int b = 0; b < B; b++) {
            int bi = 0;
            for (int e = 1; e < NE; e++)
                if (logits[b][e] > logits[b][bi]) bi = e;
            d_eidx[b] = bi;
            dens[bi] += 1.f / B;
            float mx = logits[b][0];
            for (int e = 1; e < NE; e++) mx = fmaxf(mx, logits[b][e]);
            float ex[NE], sum = 0.f;
            for (int e = 0; e < NE; e++) { ex[e] = expf(logits[b][e] - mx); sum += ex[e]; }
            for (int e = 0; e < NE; e++) proxy[e] += ex[e] / sum * (1.f / B);
        }
        float aux = 0.f;
        for (int e = 0; e < NE; e++) aux += dens[e] * proxy[e];
        *out_loss = 0.01f * aux * (float)NE;
    }
}

// ---------------------------------------------------------------------------
// Kernel 4: 3x3 s2 conv, 64 -> 128.  Epilogue writes NHWC bf16x2.
// ---------------------------------------------------------------------------
__global__ void __launch_bounds__(128, 4)
conv2_kernel(const float* __restrict__ w_all)
{
    const int oy  = blockIdx.x * 8 + (threadIdx.x >> 4);
    const int ocg = blockIdx.y;
    const int b   = blockIdx.z;
    const int l   = threadIdx.x & 15;

    const float* w = w_all + ((long)d_eidx[b] * C2 + ocg * 8) * CONV2_K;
    __shared__ __align__(16) float wsm[CONV2_K][8];
    for (int idx = threadIdx.x; idx < 8 * CONV2_K; idx += 128) {
        const int o = idx / CONV2_K;
        const int k = idx - o * CONV2_K;
        wsm[k][o] = w[idx];
    }
    __syncthreads();

    unsigned long long acc[8][4];
#pragma unroll
    for (int p = 0; p < 8; p++)
#pragma unroll
        for (int j = 0; j < 4; j++) acc[p][j] = 0ull;

    const float* ib = d_ebuf1p + (long)b * C1 * (E1R * E1W);
#pragma unroll 1
    for (int ic = 0; ic < C1; ic++) {
        const float* xc = ib + (long)ic * (E1R * E1W);
#pragma unroll
        for (int ky = 0; ky < 3; ky++) {
            const float* row = xc + (2 * oy + ky) * E1W;
            const float4 e0 = *(const float4*)(row + 8 * l);
            const float4 e1 = *(const float4*)(row + 8 * l + 4);
            const float4 q0 = *(const float4*)(row + 128 + 8 * l);
            const float4 q1 = *(const float4*)(row + 128 + 8 * l + 4);
            const float4 q2 = *(const float4*)(row + 128 + 8 * l + 8);
            const float E[8]  = {e0.x, e0.y, e0.z, e0.w, e1.x, e1.y, e1.z, e1.w};
            const float O[12] = {q0.x, q0.y, q0.z, q0.w, q1.x, q1.y, q1.z, q1.w,
                                 q2.x, q2.y, q2.z, q2.w};
            const int kb = (ic * 3 + ky) * 3;
#pragma unroll
            for (int kx = 0; kx < 3; kx++) {
                const ulonglong2* wp = (const ulonglong2*)wsm[kb + kx];
                const ulonglong2 wA = wp[0], wB = wp[1];
#pragma unroll
                for (int p = 0; p < 8; p++) {
                    const float v = (kx == 1) ? E[p] : ((kx == 0) ? O[p] : O[p + 1]);
                    const unsigned long long vv = pack2(v);
                    FFMA2_8(acc[p], vv, wA, wB);
                }
            }
        }
    }

    // NHWC bf16x2 epilogue: [b][oy+1][px+1][oc], oc = ocg*8 + 0..7
#pragma unroll
    for (int p = 0; p < 8; p++) {
        __align__(16) __nv_bfloat16 hi8[8];
        __align__(16) __nv_bfloat16 lo8[8];
#pragma unroll
        for (int j = 0; j < 4; j++) {
            const float va = fmaxf(f2lo(acc[p][j]), 0.f);
            const float vb = fmaxf(f2hi(acc[p][j]), 0.f);
            const __nv_bfloat16 ha = __float2bfloat16(va);
            const __nv_bfloat16 hb = __float2bfloat16(vb);
            hi8[2 * j]     = ha;
            lo8[2 * j]     = __float2bfloat16(va - __bfloat162float(ha));
            hi8[2 * j + 1] = hb;
            lo8[2 * j + 1] = __float2bfloat16(vb - __bfloat162float(hb));
        }
        const long off = (((long)b * AR + (oy + 1)) * AW + (8 * l + p + 1)) * C2
                       + ocg * 8;
        *(uint4*)(d_act_hi + off) = *(const uint4*)hi8;
        *(uint4*)(d_act_lo + off) = *(const uint4*)lo8;
    }
}

// ---------------------------------------------------------------------------
// Kernel 5: head1 via mma.sync bf16x2 + smem staging + ldmatrix.
// Grid (128 rows, 8 batch), 256 threads = 8 warps (4 px-tiles x 2 oc-halves).
// Per shift: stage 4 contiguous 32KB tiles (A hi/lo px-major, B hi/lo oc-major)
// into 272B-pitched smem; feed fragments with ldmatrix (conflict-free).
// ---------------------------------------------------------------------------
#define PITCHB   272                     // bytes per smem tile row (256 + 16 pad)
#define TILE_B   (128 * PITCHB)          // 34816 bytes
#define OFF_AH   0
#define OFF_AL   TILE_B
#define OFF_BH   (2 * TILE_B)
#define OFF_BL   (3 * TILE_B)
#define HEAD1_SMEM (4 * TILE_B)          // 139264 bytes

__global__ void __launch_bounds__(256)
head1_mma_kernel(const float* __restrict__ b_all)
{
    extern __shared__ __align__(16) char sm[];
    const int oy   = blockIdx.x;
    const int b    = blockIdx.y;
    const int t    = threadIdx.x;
    const int wid  = t >> 5;
    const int lane = t & 31;
    const int g    = lane >> 2;           // groupID 0..7
    const int tg   = lane & 3;            // thread-in-group 0..3
    const int e    = d_eidx[b];
    const int px0  = (wid & 3) * 32;      // warp px tile
    const int ocq  = (wid >> 2) * 64;     // warp oc half

    const uint32_t smb = smem_u32(sm);
    // ldmatrix lane base addresses (bytes), advanced by 32 per kstep
    const uint32_t aRow = (uint32_t)(px0 + (lane & 15)) * PITCHB + ((lane >> 4) * 16);
    const uint32_t bRow = (uint32_t)(ocq + (lane & 7)) * PITCHB + (((lane >> 3) & 1) * 16);
    const uint32_t aAH0 = smb + OFF_AH + aRow;
    const uint32_t aAL0 = smb + OFF_AL + aRow;
    const uint32_t aBH0 = smb + OFF_BH + bRow;
    const uint32_t aBL0 = smb + OFF_BL + bRow;

    float acc[2][8][4];
#pragma unroll
    for (int mt = 0; mt < 2; mt++)
#pragma unroll
        for (int nt = 0; nt < 8; nt++)
#pragma unroll
            for (int j = 0; j < 4; j++) acc[mt][nt][j] = 0.f;

#pragma unroll 1
    for (int s = 0; s < 9; s++) {
        const int dy = s / 3, dx = s - 3 * dy;
        const uint4* srcAH = (const uint4*)(d_act_hi + (((long)b * AR + (oy + dy)) * AW + dx) * C2);
        const uint4* srcAL = (const uint4*)(d_act_lo + (((long)b * AR + (oy + dy)) * AW + dx) * C2);
        const uint4* srcBH = (const uint4*)(d_w1h + (long)(e * 9 + s) * (C2 * C2));
        const uint4* srcBL = (const uint4*)(d_w1l + (long)(e * 9 + s) * (C2 * C2));

        if (s) __syncthreads();          // prior ldmatrix reads complete
        // stage 4 x 32KB (each source block is contiguous); dst pitched 272B
#pragma unroll 1
        for (int idx = t; idx < 2048; idx += 256) {
            const int row = idx >> 4, ch = idx & 15;
            const int d0  = row * PITCHB + (ch << 4);
            *(uint4*)(sm + OFF_AH + d0) = srcAH[idx];
            *(uint4*)(sm + OFF_AL + d0) = srcAL[idx];
            *(uint4*)(sm + OFF_BH + d0) = srcBH[idx];
            *(uint4*)(sm + OFF_BL + d0) = srcBL[idx];
        }
        __syncthreads();

#pragma unroll 1
        for (int ks = 0; ks < 8; ks++) {
            const uint32_t ko = (uint32_t)(32 * ks);
            uint32_t AH[2][4], AL[2][4];
#pragma unroll
            for (int mt = 0; mt < 2; mt++) {
                ldm_x4(AH[mt], aAH0 + ko + (uint32_t)(mt * 16 * PITCHB));
                ldm_x4(AL[mt], aAL0 + ko + (uint32_t)(mt * 16 * PITCHB));
            }
#pragma unroll
            for (int nt = 0; nt < 8; nt++) {
                uint32_t BH0, BH1, BL0, BL1;
                ldm_x2(BH0, BH1, aBH0 + ko + (uint32_t)(nt * 8 * PITCHB));
                ldm_x2(BL0, BL1, aBL0 + ko + (uint32_t)(nt * 8 * PITCHB));
#pragma unroll
                for (int mt = 0; mt < 2; mt++) {
                    mma_bf16(acc[mt][nt], AH[mt][0], AH[mt][1], AH[mt][2], AH[mt][3], BH0, BH1);
                    mma_bf16(acc[mt][nt], AH[mt][0], AH[mt][1], AH[mt][2], AH[mt][3], BL0, BL1);
                    mma_bf16(acc[mt][nt], AL[mt][0], AL[mt][1], AL[mt][2], AL[mt][3], BH0, BH1);
                }
            }
        }
    }

    // Epilogue: D frag (mt,nt): rows px0+mt*16+g (+8), cols ocq+nt*8+2tg (+1)
#pragma unroll
    for (int nt = 0; nt < 8; nt++) {
        const int oc0 = ocq + nt * 8 + 2 * tg;
        const float bias0 = b_all[e * C2 + oc0];
        const float bias1 = b_all[e * C2 + oc0 + 1];
        float* o0 = d_ebuf3 + ((long)(b * C2 + oc0) * H2 + oy) * W2;
        float* o1 = d_ebuf3 + ((long)(b * C2 + oc0 + 1) * H2 + oy) * W2;
#pragma unroll
        for (int mt = 0; mt < 2; mt++) {
            const int px = px0 + mt * 16 + g;
            o0[px]     = fmaxf(acc[mt][nt][0] + bias0, 0.f);
            o1[px]     = fmaxf(acc[mt][nt][1] + bias1, 0.f);
            o0[px + 8] = fmaxf(acc[mt][nt][2] + bias0, 0.f);
            o1[px + 8] = fmaxf(acc[mt][nt][3] + bias1, 0.f);
        }
    }
}

// ---------------------------------------------------------------------------
// Kernel 6: 1x1 conv 128 -> 5 + bias, scatter into (hm, wh, reg) layout.
// ---------------------------------------------------------------------------
__global__ void __launch_bounds__(128)
head2_kernel(const float* __restrict__ w_all,
             const float* __restrict__ b_all,
             float* __restrict__ out)
{
    const int oy = blockIdx.x;
    const int b  = blockIdx.y;
    const int ox = threadIdx.x;
    const int e  = d_eidx[b];

    __shared__ __align__(16) float ws[C2][8];
    for (int idx = threadIdx.x; idx < 5 * C2; idx += 128) {
        const int j = idx / C2, ic = idx - j * C2;
        ws[ic][j] = w_all[(long)e * 5 * C2 + idx];
    }
    __syncthreads();

    float acc[5] = {0.f, 0.f, 0.f, 0.f, 0.f};
    const float* ib = d_ebuf3 + (long)b * C2 * H2 * W2 + oy * W2 + ox;
    for (int ic = 0; ic < C2; ic++) {
        const float v = __ldg(ib + ic * (H2 * W2));
        const float4 w4 = *(const float4*)ws[ic];
        acc[0] += v * w4.x;
        acc[1] += v * w4.y;
        acc[2] += v * w4.z;
        acc[3] += v * w4.w;
        acc[4] += v * ws[ic][4];
    }

    const int p  = oy * W2 + ox;
    const int HW = H2 * W2;
    const float* bb = b_all + e * 5;
    out[b * HW + p]                        = acc[0] + bb[0];
    out[B * HW + (b * 2 + 0) * HW + p]     = acc[1] + bb[1];
    out[B * HW + (b * 2 + 1) * HW + p]     = acc[2] + bb[2];
    out[3 * B * HW + (b * 2 + 0) * HW + p] = acc[3] + bb[3];
    out[3 * B * HW + (b * 2 + 1) * HW + p] = acc[4] + bb[4];
}

// ---------------------------------------------------------------------------
// Launch
// ---------------------------------------------------------------------------
extern "C" void kernel_launch(void* const* d_in, const int* in_sizes, int n_in,
                              void* d_out, int out_size)
{
    const float* x        = (const float*)d_in[0];
    const float* g_conv_w = (const float*)d_in[1];
    const float* g_gamma  = (const float*)d_in[2];
    const float* g_beta   = (const float*)d_in[3];
    const float* g_mean   = (const float*)d_in[4];
    const float* g_var    = (const float*)d_in[5];
    const float* g_fc_w   = (const float*)d_in[6];
    const float* g_fc_b   = (const float*)d_in[7];
    const float* e_conv1  = (const float*)d_in[8];
    const float* e_conv2  = (const float*)d_in[9];
    const float* e_hw1    = (const float*)d_in[10];
    const float* e_hb1    = (const float*)d_in[11];
    const float* e_hw2    = (const float*)d_in[12];
    const float* e_hb2    = (const float*)d_in[13];
    float* out = (float*)d_out;

    cudaFuncSetAttribute(head1_mma_kernel,
                         cudaFuncAttributeMaxDynamicSharedMemorySize,
                         HEAD1_SMEM);

    // 0. Pad/deinterleave input + halos + head1 weight bf16x2 split
    prep_kernel<<<PREP_W, 256>>>(x, e_hw1);
    // 1. Gating conv (7x7 s2) + BN + ReLU
    conv7x7_kernel<true><<<dim3(64, 8, B), 128>>>(g_conv_w, g_gamma, g_beta, g_mean, g_var);
    // 2. Maxpool + global average
    pool_mean_kernel<<<B * C1, 256>>>();
    // 3. Logits, top-1 expert selection, aux loss
    gate_finalize_kernel<<<1, 32>>>(g_fc_w, g_fc_b, out + (out_size - 1));
    // 4. Selected expert conv1 (7x7 s2) + ReLU -> ebuf1p (deinterleaved)
    conv7x7_kernel<false><<<dim3(64, 8, B), 128>>>(e_conv1, nullptr, nullptr, nullptr, nullptr);
    // 5. Expert conv2 (3x3 s2) + ReLU -> NHWC bf16x2
    conv2_kernel<<<dim3(16, 16, B), 128>>>(e_conv2);
    // 6. Head conv1 via mma.sync + ldmatrix bf16x2 implicit GEMM -> ebuf3
    head1_mma_kernel<<<dim3(H2, B), 256, HEAD1_SMEM>>>(e_hb1);
    // 7. Head conv2 (1x1) + bias, scattered to (hm, wh, reg)
    head2_kernel<<<dim3(128, B), 128>>>(e_hw2, e_hb2, out);
}

// round 15
// speedup vs baseline: 1.3677x; 1.1429x over previous
#include <cuda_runtime.h>
#include <cuda_bf16.h>
#include <math.h>
#include <stdint.h>

// ---------------------------------------------------------------------------
// Problem constants
// ---------------------------------------------------------------------------
#define B        8
#define CIN      15          // 3*5 after reshape
#define C1       64
#define H0       512
#define W0       512
#define H1       256
#define W1       256
#define C2       128
#define H2       128
#define W2       128
#define NE       3
#define CONV1_K  (CIN*7*7)   // 735
#define CONV2_K  (C1*3*3)    // 576

// Deinterleaved padded fp32 input (gating conv): [even 260 | odd 260], 520 rows
#define XW  520
#define XR  520
// ebuf1 (conv1 out, 256x256) deinterleaved fp32: row = iy+1 (258 rows),
// [even 128 | odd 132] = 260 floats
#define E1R 258
#define E1W 260
// NHWC padded activation for head1 (conv2 out): [B][130][132][128] bf16 x2
#define AR 130
#define AW 132
// NHWC-16 even/odd deinterleaved padded input for conv1 MMA:
// per (b,row): 520 entries x 16 ch bf16.  row = iy+3 (0..516, alloc 520).
//   entry c<260:  e = c-1,  ix = 2e      (pads zero)
//   entry c>=260: o = c-262, ix = 2o+1
#define XNW 520

// ---------------------------------------------------------------------------
// Device scratch
// ---------------------------------------------------------------------------
__device__ __align__(16) float d_xpad  [(long)B*CIN*XR*XW];
__device__ __align__(16) float d_gbuf  [(long)B*C1*H1*W1];
__device__ __align__(16) float d_ebuf1p[(long)B*C1*E1R*E1W];
__device__ __align__(16) __nv_bfloat16 d_xnh_h[(long)B*520*XNW*16];
__device__ __align__(16) __nv_bfloat16 d_xnh_l[(long)B*520*XNW*16];
__device__ __align__(16) __nv_bfloat16 d_w1c_h[NE*7*7*C1*16];
__device__ __align__(16) __nv_bfloat16 d_w1c_l[NE*7*7*C1*16];
__device__ __align__(16) __nv_bfloat16 d_act_hi[(long)B*AR*AW*C2];
__device__ __align__(16) __nv_bfloat16 d_act_lo[(long)B*AR*AW*C2];
__device__ __align__(16) __nv_bfloat16 d_w1h[NE*9*C2*C2];
__device__ __align__(16) __nv_bfloat16 d_w1l[NE*9*C2*C2];
__device__ __align__(16) float d_ebuf3 [(long)B*C2*H2*W2];
__device__ float d_pooled[B*C1];
__device__ int   d_eidx[B];

// ---------------------------------------------------------------------------
// Packed f32x2 helpers
// ---------------------------------------------------------------------------
__device__ __forceinline__ unsigned long long pack2(float v) {
    unsigned long long r;
    asm("mov.b64 %0, {%1, %1};" : "=l"(r) : "f"(v));
    return r;
}
__device__ __forceinline__ void ffma2(unsigned long long& d,
                                      unsigned long long a,
                                      unsigned long long b) {
    asm("fma.rn.f32x2 %0, %1, %2, %0;" : "+l"(d) : "l"(a), "l"(b));
}
__device__ __forceinline__ float f2lo(unsigned long long v) {
    return __uint_as_float((unsigned int)v);
}
__device__ __forceinline__ float f2hi(unsigned long long v) {
    return __uint_as_float((unsigned int)(v >> 32));
}

#define FFMA2_8(accp, vv, wA, wB) do {                                \
    ffma2((accp)[0], (vv), (wA).x); ffma2((accp)[1], (vv), (wA).y);   \
    ffma2((accp)[2], (vv), (wB).x); ffma2((accp)[3], (vv), (wB).y);   \
} while (0)

// ---------------------------------------------------------------------------
// Warp-level bf16 MMA + ldmatrix (baseline PTX ISA)
// ---------------------------------------------------------------------------
__device__ __forceinline__ void mma_bf16(float* d,
                                         uint32_t a0, uint32_t a1,
                                         uint32_t a2, uint32_t a3,
                                         uint32_t b0, uint32_t b1)
{
    asm volatile(
        "mma.sync.aligned.m16n8k16.row.col.f32.bf16.bf16.f32 "
        "{%0,%1,%2,%3}, {%4,%5,%6,%7}, {%8,%9}, {%0,%1,%2,%3};"
        : "+f"(d[0]), "+f"(d[1]), "+f"(d[2]), "+f"(d[3])
        : "r"(a0), "r"(a1), "r"(a2), "r"(a3), "r"(b0), "r"(b1));
}
__device__ __forceinline__ void ldm_x4(uint32_t* r, uint32_t addr)
{
    asm volatile("ldmatrix.sync.aligned.m8n8.x4.shared.b16 {%0,%1,%2,%3}, [%4];"
                 : "=r"(r[0]), "=r"(r[1]), "=r"(r[2]), "=r"(r[3]) : "r"(addr));
}
__device__ __forceinline__ void ldm_x2(uint32_t& r0, uint32_t& r1, uint32_t addr)
{
    asm volatile("ldmatrix.sync.aligned.m8n8.x2.shared.b16 {%0,%1}, [%2];"
                 : "=r"(r0), "=r"(r1) : "r"(addr));
}
__device__ __forceinline__ uint32_t smem_u32(const void* p) {
    uint32_t a;
    asm("{ .reg .u64 t; cvta.to.shared.u64 t, %1; cvt.u32.u64 %0, t; }"
        : "=r"(a) : "l"(p));
    return a;
}

// ---------------------------------------------------------------------------
// Kernel 0: prep — all layout transforms (one launch)
// ---------------------------------------------------------------------------
#define PREP_X    (B*CIN*XR)             // xpad rows (gating)
#define PREP_XN   (PREP_X + B*520)       // NHWC-16 input rows (conv1 mma)
#define PREP_E1   (PREP_XN + B*C1)       // ebuf1p halos
#define PREP_ACT  (PREP_E1 + B)          // act_hi/lo halos
#define PREP_W    (PREP_ACT + NE*9)      // head1 weight split
#define PREP_W1   (PREP_W + NE*7)        // conv1 weight split (per e,ky)

__global__ void __launch_bounds__(256)
prep_kernel(const float* __restrict__ x,
            const float* __restrict__ e_hw1,
            const float* __restrict__ e_conv1)
{
    const int blk = blockIdx.x;
    const int t   = threadIdx.x;
    if (blk < PREP_X) {
        const int bc = blk / XR;
        const int r  = blk - bc * XR;
        const int iy = r - 3;
        float* dst = d_xpad + (long)blk * XW;
        const bool rowok = (unsigned)iy < (unsigned)H0;
        if (!rowok) {
            for (int c = t; c < XW; c += 256) dst[c] = 0.f;
        } else {
            const float* src = x + (long)bc * (H0 * W0) + (long)iy * W0;
            if (t < 128) {
                const float4 v = *(const float4*)(src + 4 * t);
                dst[1 + 2 * t]       = v.x;
                dst[2 + 2 * t]       = v.z;
                dst[260 + 2 + 2 * t] = v.y;
                dst[260 + 3 + 2 * t] = v.w;
            } else if (t == 128) {
                dst[0] = 0.f; dst[257] = 0.f; dst[258] = 0.f; dst[259] = 0.f;
                dst[260] = 0.f; dst[261] = 0.f; dst[518] = 0.f; dst[519] = 0.f;
            }
        }
    } else if (blk < PREP_XN) {
        // NHWC-16 deinterleaved padded input, bf16 hi/lo
        const int bb  = (blk - PREP_X) / 520;
        const int row = (blk - PREP_X) - bb * 520;
        const int iy  = row - 3;
        const bool rowok = (unsigned)iy < (unsigned)H0;
        __nv_bfloat16* H = d_xnh_h + (long)(blk - PREP_X) * (XNW * 16);
        __nv_bfloat16* L = d_xnh_l + (long)(blk - PREP_X) * (XNW * 16);
        for (int c = t; c < XNW; c += 256) {
            const int ix = (c < 260) ? (2 * c - 2) : (2 * c - 523);
            const bool ok = rowok && (unsigned)ix < (unsigned)W0;
            __align__(16) __nv_bfloat16 h16[16], l16[16];
#pragma unroll
            for (int ch = 0; ch < 16; ch++) {
                float v = 0.f;
                if (ok && ch < CIN)
                    v = x[((long)(bb * CIN + ch)) * (H0 * W0) + (long)iy * W0 + ix];
                const __nv_bfloat16 h = __float2bfloat16(v);
                h16[ch] = h;
                l16[ch] = __float2bfloat16(v - __bfloat162float(h));
            }
            *(uint4*)(H + c * 16)     = *(const uint4*)h16;
            *(uint4*)(H + c * 16 + 8) = *(const uint4*)(h16 + 8);
            *(uint4*)(L + c * 16)     = *(const uint4*)l16;
            *(uint4*)(L + c * 16 + 8) = *(const uint4*)(l16 + 8);
        }
    } else if (blk < PREP_E1) {
        float* p = d_ebuf1p + (long)(blk - PREP_XN) * (E1R * E1W);
        for (int i = t; i < E1W; i += 256) p[i] = 0.f;      // row 0
        {
            float* r = p + (t + 1) * E1W;                   // rows 1..256
            r[128] = 0.f;
            r[257] = 0.f; r[258] = 0.f; r[259] = 0.f;
        }
    } else if (blk < PREP_ACT) {
        const int bb = blk - PREP_E1;
        const uint4 z = make_uint4(0, 0, 0, 0);
        for (int pl = 0; pl < 2; pl++) {
            __nv_bfloat16* A = pl ? d_act_lo : d_act_hi;
            uint4* r0 = (uint4*)(A + ((long)bb * AR + 0) * AW * C2);
            uint4* r1 = (uint4*)(A + ((long)bb * AR + 129) * AW * C2);
            for (int i = t; i < AW * C2 / 8; i += 256) { r0[i] = z; r1[i] = z; }
            for (int i = t; i < 128 * 2 * 16; i += 256) {
                const int py  = 1 + (i >> 5);
                const int rem = i & 31;
                const int px  = (rem & 16) ? 129 : 0;
                const int ch  = rem & 15;
                *((uint4*)(A + (((long)bb * AR + py) * AW + px) * C2) + ch) = z;
            }
        }
    } else if (blk < PREP_W) {
        // head1 weight split: d_w1{h,l}[e][s][oc][ic]
        const int ws = blk - PREP_ACT;
        const int e  = ws / 9;
        const int s  = ws - e * 9;
        __nv_bfloat16* WH = d_w1h + (long)ws * (C2 * C2);
        __nv_bfloat16* WL = d_w1l + (long)ws * (C2 * C2);
        for (int i = t; i < C2 * C2; i += 256) {
            const int oc = i >> 7, ic = i & 127;
            const float w = e_hw1[(((long)e * C2 + oc) * C2 + ic) * 9 + s];
            const __nv_bfloat16 h = __float2bfloat16(w);
            WH[i] = h;
            WL[i] = __float2bfloat16(w - __bfloat162float(h));
        }
    } else {
        // conv1 weight split: d_w1c[e][ky][kx*64+oc][ch16]
        const int ws = blk - PREP_W;           // 0..20
        const int e  = ws / 7;
        const int ky = ws - e * 7;
        __nv_bfloat16* WH = d_w1c_h + (long)ws * (7 * C1 * 16);
        __nv_bfloat16* WL = d_w1c_l + (long)ws * (7 * C1 * 16);
        for (int i = t; i < 7 * C1 * 16; i += 256) {
            const int kx = i >> 10;            // /1024
            const int rem = i & 1023;
            const int oc = rem >> 4, ch = rem & 15;
            float w = 0.f;
            if (ch < CIN)
                w = e_conv1[(((long)(e * C1 + oc) * CIN + ch) * 49) + ky * 7 + kx];
            const __nv_bfloat16 h = __float2bfloat16(w);
            WH[i] = h;
            WL[i] = __float2bfloat16(w - __bfloat162float(h));
        }
    }
}

// ---------------------------------------------------------------------------
// Kernel 1: 7x7 s2 conv, 15 -> 64, scalar fp32 (GATING ONLY — exact argmax).
// ---------------------------------------------------------------------------
__global__ void __launch_bounds__(128, 4)
conv7x7_gating_kernel(const float* __restrict__ w_all,
                      const float* __restrict__ bn_gamma,
                      const float* __restrict__ bn_beta,
                      const float* __restrict__ bn_mean,
                      const float* __restrict__ bn_var)
{
    const int oy  = blockIdx.x * 4 + (threadIdx.x >> 5);
    const int ocg = blockIdx.y;
    const int b   = blockIdx.z;
    const int l   = threadIdx.x & 31;

    const float* w = w_all + (long)ocg * 8 * CONV1_K;

    __shared__ __align__(16) float wsm[CONV1_K][8];
    for (int idx = threadIdx.x; idx < 8 * CONV1_K; idx += 128) {
        const int o = idx / CONV1_K;
        const int k = idx - o * CONV1_K;
        wsm[k][o] = w[idx];
    }
    __syncthreads();

    unsigned long long acc[8][4];
#pragma unroll
    for (int p = 0; p < 8; p++)
#pragma unroll
        for (int j = 0; j < 4; j++) acc[p][j] = 0ull;

    const float* xb = d_xpad + (long)b * CIN * (XR * XW);
#pragma unroll 1
    for (int ic = 0; ic < CIN; ic++) {
#pragma unroll 1
        for (int ky = 0; ky < 7; ky++) {
            const float* row = xb + ((long)ic * XR + (2 * oy + ky)) * XW;
            const float4 e0 = *(const float4*)(row + 8 * l);
            const float4 e1 = *(const float4*)(row + 8 * l + 4);
            const float4 e2 = *(const float4*)(row + 8 * l + 8);
            const float4 q0 = *(const float4*)(row + 260 + 8 * l);
            const float4 q1 = *(const float4*)(row + 260 + 8 * l + 4);
            const float4 q2 = *(const float4*)(row + 260 + 8 * l + 8);
            const float E[12] = {e0.x, e0.y, e0.z, e0.w, e1.x, e1.y, e1.z, e1.w,
                                 e2.x, e2.y, e2.z, e2.w};
            const float O[12] = {q0.x, q0.y, q0.z, q0.w, q1.x, q1.y, q1.z, q1.w,
                                 q2.x, q2.y, q2.z, q2.w};
            const int kb = (ic * 7 + ky) * 7;
#pragma unroll
            for (int kx = 0; kx < 7; kx++) {
                const ulonglong2* wp = (const ulonglong2*)wsm[kb + kx];
                const ulonglong2 wA = wp[0], wB = wp[1];
#pragma unroll
                for (int p = 0; p < 8; p++) {
                    const float v = (kx & 1) ? E[p + ((kx - 1) >> 1)]
                                             : O[p + (kx >> 1)];
                    const unsigned long long vv = pack2(v);
                    FFMA2_8(acc[p], vv, wA, wB);
                }
            }
        }
    }

#pragma unroll
    for (int j = 0; j < 4; j++) {
        const int oca = ocg * 8 + 2 * j;
        const int ocb = oca + 1;
        const float sa = bn_gamma[oca] * rsqrtf(bn_var[oca] + 1e-5f);
        const float sb = bn_gamma[ocb] * rsqrtf(bn_var[ocb] + 1e-5f);
        const float ta = bn_beta[oca] - bn_mean[oca] * sa;
        const float tb = bn_beta[ocb] - bn_mean[ocb] * sb;
        float4 va0, va1, vb0, vb1;
        va0.x = fmaxf(f2lo(acc[0][j]) * sa + ta, 0.f);
        va0.y = fmaxf(f2lo(acc[1][j]) * sa + ta, 0.f);
        va0.z = fmaxf(f2lo(acc[2][j]) * sa + ta, 0.f);
        va0.w = fmaxf(f2lo(acc[3][j]) * sa + ta, 0.f);
        va1.x = fmaxf(f2lo(acc[4][j]) * sa + ta, 0.f);
        va1.y = fmaxf(f2lo(acc[5][j]) * sa + ta, 0.f);
        va1.z = fmaxf(f2lo(acc[6][j]) * sa + ta, 0.f);
        va1.w = fmaxf(f2lo(acc[7][j]) * sa + ta, 0.f);
        vb0.x = fmaxf(f2hi(acc[0][j]) * sb + tb, 0.f);
        vb0.y = fmaxf(f2hi(acc[1][j]) * sb + tb, 0.f);
        vb0.z = fmaxf(f2hi(acc[2][j]) * sb + tb, 0.f);
        vb0.w = fmaxf(f2hi(acc[3][j]) * sb + tb, 0.f);
        vb1.x = fmaxf(f2hi(acc[4][j]) * sb + tb, 0.f);
        vb1.y = fmaxf(f2hi(acc[5][j]) * sb + tb, 0.f);
        vb1.z = fmaxf(f2hi(acc[6][j]) * sb + tb, 0.f);
        vb1.w = fmaxf(f2hi(acc[7][j]) * sb + tb, 0.f);
        float* pa = d_gbuf + ((long)(b * C1 + oca) * H1 + oy) * W1 + 8 * l;
        float* pb = d_gbuf + ((long)(b * C1 + ocb) * H1 + oy) * W1 + 8 * l;
        *(float4*)(pa)     = va0;  *(float4*)(pa + 4) = va1;
        *(float4*)(pb)     = vb0;  *(float4*)(pb + 4) = vb1;
    }
}

// ---------------------------------------------------------------------------
// Kernel 2: maxpool 3x3 s2 pad1 + spatial mean, per (b,c).
// ---------------------------------------------------------------------------
__global__ void pool_mean_kernel()
{
    const int bc = blockIdx.x;
    const float* p = d_gbuf + (long)bc * (H1 * W1);
    float sum = 0.f;
    for (int i = threadIdx.x; i < H2 * W2; i += blockDim.x) {
        const int py = i >> 7, px = i & 127;
        float m = -1e30f;
#pragma unroll
        for (int dy = 0; dy < 3; dy++) {
            const int iy = py * 2 - 1 + dy;
            if ((unsigned)iy >= (unsigned)H1) continue;
            const float* row = p + iy * W1;
#pragma unroll
            for (int dx = 0; dx < 3; dx++) {
                const int ix = px * 2 - 1 + dx;
                if ((unsigned)ix < (unsigned)W1) m = fmaxf(m, row[ix]);
            }
        }
        sum += m;
    }
    __shared__ float red[256];
    red[threadIdx.x] = sum;
    __syncthreads();
    for (int s = 128; s > 0; s >>= 1) {
        if (threadIdx.x < s) red[threadIdx.x] += red[threadIdx.x + s];
        __syncthreads();
    }
    if (threadIdx.x == 0) d_pooled[bc] = red[0] * (1.f / (H2 * W2));
}

// ---------------------------------------------------------------------------
// Kernel 3: FC -> logits -> top-1 expert + aux loss.
// ---------------------------------------------------------------------------
__global__ void gate_finalize_kernel(const float* __restrict__ fcw,
                                     const float* __restrict__ fcb,
                                     float* __restrict__ out_loss)
{
    __shared__ float logits[B][NE];
    const int t = threadIdx.x;
    if (t < B * NE) {
        const int b = t / NE, e = t % NE;
        float s = fcb[e];
        const float* pw = fcw + e * C1;
        const float* pp = d_pooled + b * C1;
        for (int i = 0; i < C1; i++) s += pp[i] * pw[i];
        logits[b][e] = s;
    }
    __syncthreads();
    if (t == 0) {
        float dens[NE]  = {0.f, 0.f, 0.f};
        float proxy[NE] = {0.f, 0.f, 0.f};
        for (int b = 0; b < B; b++) {
            int bi = 0;
            for (int e = 1; e < NE; e++)
                if (logits[b][e] > logits[b][bi]) bi = e;
            d_eidx[b] = bi;
            dens[bi] += 1.f / B;
            float mx = logits[b][0];
            for (int e = 1; e < NE; e++) mx = fmaxf(mx, logits[b][e]);
            float ex[NE], sum = 0.f;
            for (int e = 0; e < NE; e++) { ex[e] = expf(logits[b][e] - mx); sum += ex[e]; }
            for (int e = 0; e < NE; e++) proxy[e] += ex[e] / sum * (1.f / B);
        }
        float aux = 0.f;
        for (int e = 0; e < NE; e++) aux += dens[e] * proxy[e];
        *out_loss = 0.01f * aux * (float)NE;
    }
}

// ---------------------------------------------------------------------------
// Kernel 4: expert conv1 (7x7 s2, 15->64) via mma.sync + ldmatrix bf16x2.
// Grid (256 rows, 2 px-halves, 8 b), 256 thr = 8 warps (4 px-tiles x 2 oc-32).
// Per ky: stage A even/odd NHWC-16 slices (contiguous) + B (7 kx) weights
// into 48B-pitched smem; 7 kx x (12 ldmatrix + 24 HMMA) per warp.
// Epilogue: ReLU -> ebuf1p fp32 deinterleaved (conv2 input unchanged).
// ---------------------------------------------------------------------------
#define C1P      48                      // smem pitch (bytes) — conflict-free
#define A_EV     0                       // even rows 0..129
#define A_OD     (132*C1P)               // odd rows 0..130
#define A_PL     (264*C1P)               // 12672 B per precision plane
#define B_OF     (2*A_PL)                // B hi; lo at +B_PL
#define B_PL     (448*C1P)               // 21504 B
#define CONV1_SMEM (2*A_PL + 2*B_PL)     // 68352 B

__global__ void __launch_bounds__(256)
conv1_mma_kernel()
{
    extern __shared__ __align__(16) char sm[];
    const int oy   = blockIdx.x;          // output row 0..255
    const int xh   = blockIdx.y;          // px half
    const int b    = blockIdx.z;
    const int t    = threadIdx.x;
    const int wid  = t >> 5;
    const int lane = t & 31;
    const int g    = lane >> 2;
    const int tg   = lane & 3;
    const int e    = d_eidx[b];
    const int pxbase = xh * 128;
    const int px0  = (wid & 3) * 32;      // warp px tile (rel)
    const int och  = (wid >> 2) * 32;     // warp oc half

    const uint32_t smb   = smem_u32(sm);
    const uint32_t aLane = (uint32_t)(lane & 15) * C1P + ((lane >> 4) * 16);
    const uint32_t bLane = (uint32_t)(lane & 7) * C1P + (((lane >> 3) & 1) * 16);

    float acc[2][4][4];
#pragma unroll
    for (int mt = 0; mt < 2; mt++)
#pragma unroll
        for (int nt = 0; nt < 4; nt++)
#pragma unroll
            for (int j = 0; j < 4; j++) acc[mt][nt][j] = 0.f;

#pragma unroll 1
    for (int ky = 0; ky < 7; ky++) {
        const int row = 2 * oy + ky;      // padded row (iy+3), 0..516
        const __nv_bfloat16* sH = d_xnh_h + (long)(b * 520 + row) * (XNW * 16);
        const __nv_bfloat16* sL = d_xnh_l + (long)(b * 520 + row) * (XNW * 16);
        const uint4* eH = (const uint4*)(sH + (long)pxbase * 16);        // 130 entries
        const uint4* eL = (const uint4*)(sL + (long)pxbase * 16);
        const uint4* oH = (const uint4*)(sH + (long)(pxbase + 260) * 16); // 131 entries
        const uint4* oL = (const uint4*)(sL + (long)(pxbase + 260) * 16);
        const uint4* wH = (const uint4*)(d_w1c_h + (long)(e * 7 + ky) * (7 * C1 * 16));
        const uint4* wL = (const uint4*)(d_w1c_l + (long)(e * 7 + ky) * (7 * C1 * 16));

        if (ky) __syncthreads();
        // stage A even (260 chunks of 16B per plane)
        for (int i = t; i < 260; i += 256) {
            const int d0 = A_EV + (i >> 1) * C1P + ((i & 1) << 4);
            *(uint4*)(sm + d0)        = eH[i];
            *(uint4*)(sm + A_PL + d0) = eL[i];
        }
        // stage A odd (262 chunks)
        for (int i = t; i < 262; i += 256) {
            const int d0 = A_OD + (i >> 1) * C1P + ((i & 1) << 4);
            *(uint4*)(sm + d0)        = oH[i];
            *(uint4*)(sm + A_PL + d0) = oL[i];
        }
        // stage B (896 chunks: 448 rows x 32B)
        for (int i = t; i < 896; i += 256) {
            const int d0 = B_OF + (i >> 1) * C1P + ((i & 1) << 4);
            *(uint4*)(sm + d0)        = wH[i];
            *(uint4*)(sm + B_PL + d0) = wL[i];
        }
        __syncthreads();

#pragma unroll 1
        for (int kx = 0; kx < 7; kx++) {
            // A smem row offset for this shift (relative px rp -> row rp + off)
            const uint32_t aoff = (kx & 1)
                ? (uint32_t)(A_EV + ((kx - 1) >> 1) * C1P)
                : (uint32_t)(A_OD + (kx >> 1) * C1P);
            const uint32_t aH0 = smb + aoff + (uint32_t)px0 * C1P + aLane;
            uint32_t AH[2][4], AL[2][4];
#pragma unroll
            for (int mt = 0; mt < 2; mt++) {
                ldm_x4(AH[mt], aH0 + (uint32_t)(mt * 16 * C1P));
                ldm_x4(AL[mt], aH0 + (uint32_t)(mt * 16 * C1P) + A_PL);
            }
#pragma unroll
            for (int nt = 0; nt < 4; nt++) {
                const uint32_t bAddr = smb + B_OF
                    + (uint32_t)(kx * 64 + och + nt * 8) * C1P + bLane;
                uint32_t BH0, BH1, BL0, BL1;
                ldm_x2(BH0, BH1, bAddr);
                ldm_x2(BL0, BL1, bAddr + B_PL);
#pragma unroll
                for (int mt = 0; mt < 2; mt++) {
                    mma_bf16(acc[mt][nt], AH[mt][0], AH[mt][1], AH[mt][2], AH[mt][3], BH0, BH1);
                    mma_bf16(acc[mt][nt], AH[mt][0], AH[mt][1], AH[mt][2], AH[mt][3], BL0, BL1);
                    mma_bf16(acc[mt][nt], AL[mt][0], AL[mt][1], AL[mt][2], AL[mt][3], BH0, BH1);
                }
            }
        }
    }

    // Epilogue: ReLU -> ebuf1p deinterleaved fp32.
    // px = pxbase + px0 + mt*16 + g (+8); parity = g&1 (even bases).
#pragma unroll
    for (int nt = 0; nt < 4; nt++) {
        const int oc0 = och + nt * 8 + 2 * tg;
        float* b0 = d_ebuf1p + ((long)(b * C1 + oc0) * E1R + (oy + 1)) * E1W;
        float* b1 = d_ebuf1p + ((long)(b * C1 + oc0 + 1) * E1R + (oy + 1)) * E1W;
#pragma unroll
        for (int mt = 0; mt < 2; mt++) {
            const int px = pxbase + px0 + mt * 16 + g;
            const int pos = (g & 1) ? (129 + (px >> 1)) : (px >> 1);
            b0[pos]     = fmaxf(acc[mt][nt][0], 0.f);
            b1[pos]     = fmaxf(acc[mt][nt][1], 0.f);
            b0[pos + 4] = fmaxf(acc[mt][nt][2], 0.f);   // px+8 -> pos+4
            b1[pos + 4] = fmaxf(acc[mt][nt][3], 0.f);
        }
    }
}

// ---------------------------------------------------------------------------
// Kernel 5: 3x3 s2 conv, 64 -> 128.  Epilogue writes NHWC bf16x2.
// ---------------------------------------------------------------------------
__global__ void __launch_bounds__(128, 4)
conv2_kernel(const float* __restrict__ w_all)
{
    const int oy  = blockIdx.x * 8 + (threadIdx.x >> 4);
    const int ocg = blockIdx.y;
    const int b   = blockIdx.z;
    const int l   = threadIdx.x & 15;

    const float* w = w_all + ((long)d_eidx[b] * C2 + ocg * 8) * CONV2_K;
    __shared__ __align__(16) float wsm[CONV2_K][8];
    for (int idx = threadIdx.x; idx < 8 * CONV2_K; idx += 128) {
        const int o = idx / CONV2_K;
        const int k = idx - o * CONV2_K;
        wsm[k][o] = w[idx];
    }
    __syncthreads();

    unsigned long long acc[8][4];
#pragma unroll
    for (int p = 0; p < 8; p++)
#pragma unroll
        for (int j = 0; j < 4; j++) acc[p][j] = 0ull;

    const float* ib = d_ebuf1p + (long)b * C1 * (E1R * E1W);
#pragma unroll 1
    for (int ic = 0; ic < C1; ic++) {
        const float* xc = ib + (long)ic * (E1R * E1W);
#pragma unroll
        for (int ky = 0; ky < 3; ky++) {
            const float* row = xc + (2 * oy + ky) * E1W;
            const float4 e0 = *(const float4*)(row + 8 * l);
            const float4 e1 = *(const float4*)(row + 8 * l + 4);
            const float4 q0 = *(const float4*)(row + 128 + 8 * l);
            const float4 q1 = *(const float4*)(row + 128 + 8 * l + 4);
            const float4 q2 = *(const float4*)(row + 128 + 8 * l + 8);
            const float E[8]  = {e0.x, e0.y, e0.z, e0.w, e1.x, e1.y, e1.z, e1.w};
            const float O[12] = {q0.x, q0.y, q0.z, q0.w, q1.x, q1.y, q1.z, q1.w,
                                 q2.x, q2.y, q2.z, q2.w};
            const int kb = (ic * 3 + ky) * 3;
#pragma unroll
            for (int kx = 0; kx < 3; kx++) {
                const ulonglong2* wp = (const ulonglong2*)wsm[kb + kx];
                const ulonglong2 wA = wp[0], wB = wp[1];
#pragma unroll
                for (int p = 0; p < 8; p++) {
                    const float v = (kx == 1) ? E[p] : ((kx == 0) ? O[p] : O[p + 1]);
                    const unsigned long long vv = pack2(v);
                    FFMA2_8(acc[p], vv, wA, wB);
                }
            }
        }
    }

#pragma unroll
    for (int p = 0; p < 8; p++) {
        __align__(16) __nv_bfloat16 hi8[8];
        __align__(16) __nv_bfloat16 lo8[8];
#pragma unroll
        for (int j = 0; j < 4; j++) {
            const float va = fmaxf(f2lo(acc[p][j]), 0.f);
            const float vb = fmaxf(f2hi(acc[p][j]), 0.f);
            const __nv_bfloat16 ha = __float2bfloat16(va);
            const __nv_bfloat16 hb = __float2bfloat16(vb);
            hi8[2 * j]     = ha;
            lo8[2 * j]     = __float2bfloat16(va - __bfloat162float(ha));
            hi8[2 * j + 1] = hb;
            lo8[2 * j + 1] = __float2bfloat16(vb - __bfloat162float(hb));
        }
        const long off = (((long)b * AR + (oy + 1)) * AW + (8 * l + p + 1)) * C2
                       + ocg * 8;
        *(uint4*)(d_act_hi + off) = *(const uint4*)hi8;
        *(uint4*)(d_act_lo + off) = *(const uint4*)lo8;
    }
}

// ---------------------------------------------------------------------------
// Kernel 6: head1 via mma.sync bf16x2 + smem staging + ldmatrix (R14, proven)
// ---------------------------------------------------------------------------
#define PITCHB   272
#define TILE_B   (128 * PITCHB)
#define OFF_AH   0
#define OFF_AL   TILE_B
#define OFF_BH   (2 * TILE_B)
#define OFF_BL   (3 * TILE_B)
#define HEAD1_SMEM (4 * TILE_B)

__global__ void __launch_bounds__(256)
head1_mma_kernel(const float* __restrict__ b_all)
{
    extern __shared__ __align__(16) char sm[];
    const int oy   = blockIdx.x;
    const int b    = blockIdx.y;
    const int t    = threadIdx.x;
    const int wid  = t >> 5;
    const int lane = t & 31;
    const int g    = lane >> 2;
    const int tg   = lane & 3;
    const int e    = d_eidx[b];
    const int px0  = (wid & 3) * 32;
    const int ocq  = (wid >> 2) * 64;

    const uint32_t smb = smem_u32(sm);
    const uint32_t aRow = (uint32_t)(px0 + (lane & 15)) * PITCHB + ((lane >> 4) * 16);
    const uint32_t bRow = (uint32_t)(ocq + (lane & 7)) * PITCHB + (((lane >> 3) & 1) * 16);
    const uint32_t aAH0 = smb + OFF_AH + aRow;
    const uint32_t aAL0 = smb + OFF_AL + aRow;
    const uint32_t aBH0 = smb + OFF_BH + bRow;
    const uint32_t aBL0 = smb + OFF_BL + bRow;

    float acc[2][8][4];
#pragma unroll
    for (int mt = 0; mt < 2; mt++)
#pragma unroll
        for (int nt = 0; nt < 8; nt++)
#pragma unroll
            for (int j = 0; j < 4; j++) acc[mt][nt][j] = 0.f;

#pragma unroll 1
    for (int s = 0; s < 9; s++) {
        const int dy = s / 3, dx = s - 3 * dy;
        const uint4* srcAH = (const uint4*)(d_act_hi + (((long)b * AR + (oy + dy)) * AW + dx) * C2);
        const uint4* srcAL = (const uint4*)(d_act_lo + (((long)b * AR + (oy + dy)) * AW + dx) * C2);
        const uint4* srcBH = (const uint4*)(d_w1h + (long)(e * 9 + s) * (C2 * C2));
        const uint4* srcBL = (const uint4*)(d_w1l + (long)(e * 9 + s) * (C2 * C2));

        if (s) __syncthreads();
#pragma unroll 1
        for (int idx = t; idx < 2048; idx += 256) {
            const int row = idx >> 4, ch = idx & 15;
            const int d0  = row * PITCHB + (ch << 4);
            *(uint4*)(sm + OFF_AH + d0) = srcAH[idx];
            *(uint4*)(sm + OFF_AL + d0) = srcAL[idx];
            *(uint4*)(sm + OFF_BH + d0) = srcBH[idx];
            *(uint4*)(sm + OFF_BL + d0) = srcBL[idx];
        }
        __syncthreads();

#pragma unroll 1
        for (int ks = 0; ks < 8; ks++) {
            const uint32_t ko = (uint32_t)(32 * ks);
            uint32_t AH[2][4], AL[2][4];
#pragma unroll
            for (int mt = 0; mt < 2; mt++) {
                ldm_x4(AH[mt], aAH0 + ko + (uint32_t)(mt * 16 * PITCHB));
                ldm_x4(AL[mt], aAL0 + ko + (uint32_t)(mt * 16 * PITCHB));
            }
#pragma unroll
            for (int nt = 0; nt < 8; nt++) {
                uint32_t BH0, BH1, BL0, BL1;
                ldm_x2(BH0, BH1, aBH0 + ko + (uint32_t)(nt * 8 * PITCHB));
                ldm_x2(BL0, BL1, aBL0 + ko + (uint32_t)(nt * 8 * PITCHB));
#pragma unroll
                for (int mt = 0; mt < 2; mt++) {
                    mma_bf16(acc[mt][nt], AH[mt][0], AH[mt][1], AH[mt][2], AH[mt][3], BH0, BH1);
                    mma_bf16(acc[mt][nt], AH[mt][0], AH[mt][1], AH[mt][2], AH[mt][3], BL0, BL1);
                    mma_bf16(acc[mt][nt], AL[mt][0], AL[mt][1], AL[mt][2], AL[mt][3], BH0, BH1);
                }
            }
        }
    }

#pragma unroll
    for (int nt = 0; nt < 8; nt++) {
        const int oc0 = ocq + nt * 8 + 2 * tg;
        const float bias0 = b_all[e * C2 + oc0];
        const float bias1 = b_all[e * C2 + oc0 + 1];
        float* o0 = d_ebuf3 + ((long)(b * C2 + oc0) * H2 + oy) * W2;
        float* o1 = d_ebuf3 + ((long)(b * C2 + oc0 + 1) * H2 + oy) * W2;
#pragma unroll
        for (int mt = 0; mt < 2; mt++) {
            const int px = px0 + mt * 16 + g;
            o0[px]     = fmaxf(acc[mt][nt][0] + bias0, 0.f);
            o1[px]     = fmaxf(acc[mt][nt][1] + bias1, 0.f);
            o0[px + 8] = fmaxf(acc[mt][nt][2] + bias0, 0.f);
            o1[px + 8] = fmaxf(acc[mt][nt][3] + bias1, 0.f);
        }
    }
}

// ---------------------------------------------------------------------------
// Kernel 7: 1x1 conv 128 -> 5 + bias, scatter into (hm, wh, reg) layout.
// ---------------------------------------------------------------------------
__global__ void __launch_bounds__(128)
head2_kernel(const float* __restrict__ w_all,
             const float* __restrict__ b_all,
             float* __restrict__ out)
{
    const int oy = blockIdx.x;
    const int b  = blockIdx.y;
    const int ox = threadIdx.x;
    const int e  = d_eidx[b];

    __shared__ __align__(16) float ws[C2][8];
    for (int idx = threadIdx.x; idx < 5 * C2; idx += 128) {
        const int j = idx / C2, ic = idx - j * C2;
        ws[ic][j] = w_all[(long)e * 5 * C2 + idx];
    }
    __syncthreads();

    float acc[5] = {0.f, 0.f, 0.f, 0.f, 0.f};
    const float* ib = d_ebuf3 + (long)b * C2 * H2 * W2 + oy * W2 + ox;
    for (int ic = 0; ic < C2; ic++) {
        const float v = __ldg(ib + ic * (H2 * W2));
        const float4 w4 = *(const float4*)ws[ic];
        acc[0] += v * w4.x;
        acc[1] += v * w4.y;
        acc[2] += v * w4.z;
        acc[3] += v * w4.w;
        acc[4] += v * ws[ic][4];
    }

    const int p  = oy * W2 + ox;
    const int HW = H2 * W2;
    const float* bb = b_all + e * 5;
    out[b * HW + p]                        = acc[0] + bb[0];
    out[B * HW + (b * 2 + 0) * HW + p]     = acc[1] + bb[1];
    out[B * HW + (b * 2 + 1) * HW + p]     = acc[2] + bb[2];
    out[3 * B * HW + (b * 2 + 0) * HW + p] = acc[3] + bb[3];
    out[3 * B * HW + (b * 2 + 1) * HW + p] = acc[4] + bb[4];
}

// ---------------------------------------------------------------------------
// Launch
// ---------------------------------------------------------------------------
extern "C" void kernel_launch(void* const* d_in, const int* in_sizes, int n_in,
                              void* d_out, int out_size)
{
    const float* x        = (const float*)d_in[0];
    const float* g_conv_w = (const float*)d_in[1];
    const float* g_gamma  = (const float*)d_in[2];
    const float* g_beta   = (const float*)d_in[3];
    const float* g_mean   = (const float*)d_in[4];
    const float* g_var    = (const float*)d_in[5];
    const float* g_fc_w   = (const float*)d_in[6];
    const float* g_fc_b   = (const float*)d_in[7];
    const float* e_conv1  = (const float*)d_in[8];
    const float* e_conv2  = (const float*)d_in[9];
    const float* e_hw1    = (const float*)d_in[10];
    const float* e_hb1    = (const float*)d_in[11];
    const float* e_hw2    = (const float*)d_in[12];
    const float* e_hb2    = (const float*)d_in[13];
    float* out = (float*)d_out;

    cudaFuncSetAttribute(head1_mma_kernel,
                         cudaFuncAttributeMaxDynamicSharedMemorySize,
                         HEAD1_SMEM);
    cudaFuncSetAttribute(conv1_mma_kernel,
                         cudaFuncAttributeMaxDynamicSharedMemorySize,
                         CONV1_SMEM);

    // 0. All layout prep (xpad, NHWC-16 input, halos, weight splits)
    prep_kernel<<<PREP_W1, 256>>>(x, e_hw1, e_conv1);
    // 1. Gating conv (7x7 s2) + BN + ReLU — exact fp32 (argmax safety)
    conv7x7_gating_kernel<<<dim3(64, 8, B), 128>>>(g_conv_w, g_gamma, g_beta, g_mean, g_var);
    // 2. Maxpool + global average
    pool_mean_kernel<<<B * C1, 256>>>();
    // 3. Logits, top-1 expert selection, aux loss
    gate_finalize_kernel<<<1, 32>>>(g_fc_w, g_fc_b, out + (out_size - 1));
    // 4. Expert conv1 (7x7 s2) via mma.sync bf16x2 -> ebuf1p fp32
    conv1_mma_kernel<<<dim3(256, 2, B), 256, CONV1_SMEM>>>();
    // 5. Expert conv2 (3x3 s2) + ReLU -> NHWC bf16x2
    conv2_kernel<<<dim3(16, 16, B), 128>>>(e_conv2);
    // 6. Head conv1 via mma.sync + ldmatrix bf16x2 -> ebuf3
    head1_mma_kernel<<<dim3(H2, B), 256, HEAD1_SMEM>>>(e_hb1);
    // 7. Head conv2 (1x1) + bias, scattered to (hm, wh, reg)
    head2_kernel<<<dim3(128, B), 128>>>(e_hw2, e_hb2, out);
}

// round 16
// speedup vs baseline: 1.6813x; 1.2293x over previous
#include <cuda_runtime.h>
#include <cuda_bf16.h>
#include <math.h>
#include <stdint.h>

// ---------------------------------------------------------------------------
// Problem constants
// ---------------------------------------------------------------------------
#define B        8
#define CIN      15          // 3*5 after reshape
#define C1       64
#define H0       512
#define W0       512
#define H1       256
#define W1       256
#define C2       128
#define H2       128
#define W2       128
#define NE       3
#define CONV2_K  (C1*3*3)    // 576

// ebuf1 (conv1 out, 256x256) deinterleaved fp32: row = iy+1 (258 rows),
// [even 128 | odd 132] = 260 floats
#define E1R 258
#define E1W 260
// NHWC padded activation for head1 (conv2 out): [B][130][132][128] bf16 x2
#define AR 130
#define AW 132
// NHWC-16 even/odd deinterleaved padded input (conv1 + gating MMA):
// per (b,row): 520 entries x 16 ch bf16.  row = iy+3 (0..516, alloc 520).
//   entry c<260:  e = c-1,  ix = 2e      (pads zero)
//   entry c>=260: o = c-262, ix = 2o+1
#define XNW 520

// ---------------------------------------------------------------------------
// Device scratch
// ---------------------------------------------------------------------------
__device__ __align__(16) float d_gbuf  [(long)B*C1*H1*W1];
__device__ __align__(16) float d_ebuf1p[(long)B*C1*E1R*E1W];
__device__ __align__(16) __nv_bfloat16 d_xnh_h[(long)B*520*XNW*16];
__device__ __align__(16) __nv_bfloat16 d_xnh_l[(long)B*520*XNW*16];
__device__ __align__(16) __nv_bfloat16 d_w1c_h[(NE+1)*7*7*C1*16];   // slot NE = gating
__device__ __align__(16) __nv_bfloat16 d_w1c_l[(NE+1)*7*7*C1*16];
__device__ __align__(16) __nv_bfloat16 d_act_hi[(long)B*AR*AW*C2];
__device__ __align__(16) __nv_bfloat16 d_act_lo[(long)B*AR*AW*C2];
__device__ __align__(16) __nv_bfloat16 d_w1h[NE*9*C2*C2];
__device__ __align__(16) __nv_bfloat16 d_w1l[NE*9*C2*C2];
__device__ __align__(16) float d_ebuf3 [(long)B*C2*H2*W2];
__device__ float d_pooled[B*C1];
__device__ int   d_eidx[B];

// ---------------------------------------------------------------------------
// Packed f32x2 helpers (conv2 scalar path)
// ---------------------------------------------------------------------------
__device__ __forceinline__ unsigned long long pack2(float v) {
    unsigned long long r;
    asm("mov.b64 %0, {%1, %1};" : "=l"(r) : "f"(v));
    return r;
}
__device__ __forceinline__ void ffma2(unsigned long long& d,
                                      unsigned long long a,
                                      unsigned long long b) {
    asm("fma.rn.f32x2 %0, %1, %2, %0;" : "+l"(d) : "l"(a), "l"(b));
}
__device__ __forceinline__ float f2lo(unsigned long long v) {
    return __uint_as_float((unsigned int)v);
}
__device__ __forceinline__ float f2hi(unsigned long long v) {
    return __uint_as_float((unsigned int)(v >> 32));
}

#define FFMA2_8(accp, vv, wA, wB) do {                                \
    ffma2((accp)[0], (vv), (wA).x); ffma2((accp)[1], (vv), (wA).y);   \
    ffma2((accp)[2], (vv), (wB).x); ffma2((accp)[3], (vv), (wB).y);   \
} while (0)

// ---------------------------------------------------------------------------
// Warp-level bf16 MMA + ldmatrix (baseline PTX ISA)
// ---------------------------------------------------------------------------
__device__ __forceinline__ void mma_bf16(float* d,
                                         uint32_t a0, uint32_t a1,
                                         uint32_t a2, uint32_t a3,
                                         uint32_t b0, uint32_t b1)
{
    asm volatile(
        "mma.sync.aligned.m16n8k16.row.col.f32.bf16.bf16.f32 "
        "{%0,%1,%2,%3}, {%4,%5,%6,%7}, {%8,%9}, {%0,%1,%2,%3};"
        : "+f"(d[0]), "+f"(d[1]), "+f"(d[2]), "+f"(d[3])
        : "r"(a0), "r"(a1), "r"(a2), "r"(a3), "r"(b0), "r"(b1));
}
__device__ __forceinline__ void ldm_x4(uint32_t* r, uint32_t addr)
{
    asm volatile("ldmatrix.sync.aligned.m8n8.x4.shared.b16 {%0,%1,%2,%3}, [%4];"
                 : "=r"(r[0]), "=r"(r[1]), "=r"(r[2]), "=r"(r[3]) : "r"(addr));
}
__device__ __forceinline__ void ldm_x2(uint32_t& r0, uint32_t& r1, uint32_t addr)
{
    asm volatile("ldmatrix.sync.aligned.m8n8.x2.shared.b16 {%0,%1}, [%2];"
                 : "=r"(r0), "=r"(r1) : "r"(addr));
}
__device__ __forceinline__ uint32_t smem_u32(const void* p) {
    uint32_t a;
    asm("{ .reg .u64 t; cvta.to.shared.u64 t, %1; cvt.u32.u64 %0, t; }"
        : "=r"(a) : "l"(p));
    return a;
}

// ---------------------------------------------------------------------------
// Kernel 0: prep — layout transforms (one launch; xpad path removed)
// ---------------------------------------------------------------------------
#define PREP_XN   (B*520)                // NHWC-16 input rows
#define PREP_E1   (PREP_XN + B*C1)       // ebuf1p halos
#define PREP_ACT  (PREP_E1 + B)          // act_hi/lo halos
#define PREP_W    (PREP_ACT + NE*9)      // head1 weight split
#define PREP_W1   (PREP_W + (NE+1)*7)    // conv1 weight split (experts + gating)

__global__ void __launch_bounds__(256)
prep_kernel(const float* __restrict__ x,
            const float* __restrict__ e_hw1,
            const float* __restrict__ e_conv1,
            const float* __restrict__ g_conv_w)
{
    const int blk = blockIdx.x;
    const int t   = threadIdx.x;
    if (blk < PREP_XN) {
        // NHWC-16 deinterleaved padded input, bf16 hi/lo
        const int bb  = blk / 520;
        const int row = blk - bb * 520;
        const int iy  = row - 3;
        const bool rowok = (unsigned)iy < (unsigned)H0;
        __nv_bfloat16* H = d_xnh_h + (long)blk * (XNW * 16);
        __nv_bfloat16* L = d_xnh_l + (long)blk * (XNW * 16);
        for (int c = t; c < XNW; c += 256) {
            const int ix = (c < 260) ? (2 * c - 2) : (2 * c - 523);
            const bool ok = rowok && (unsigned)ix < (unsigned)W0;
            __align__(16) __nv_bfloat16 h16[16], l16[16];
#pragma unroll
            for (int ch = 0; ch < 16; ch++) {
                float v = 0.f;
                if (ok && ch < CIN)
                    v = x[((long)(bb * CIN + ch)) * (H0 * W0) + (long)iy * W0 + ix];
                const __nv_bfloat16 h = __float2bfloat16(v);
                h16[ch] = h;
                l16[ch] = __float2bfloat16(v - __bfloat162float(h));
            }
            *(uint4*)(H + c * 16)     = *(const uint4*)h16;
            *(uint4*)(H + c * 16 + 8) = *(const uint4*)(h16 + 8);
            *(uint4*)(L + c * 16)     = *(const uint4*)l16;
            *(uint4*)(L + c * 16 + 8) = *(const uint4*)(l16 + 8);
        }
    } else if (blk < PREP_E1) {
        float* p = d_ebuf1p + (long)(blk - PREP_XN) * (E1R * E1W);
        for (int i = t; i < E1W; i += 256) p[i] = 0.f;      // row 0
        {
            float* r = p + (t + 1) * E1W;                   // rows 1..256
            r[128] = 0.f;
            r[257] = 0.f; r[258] = 0.f; r[259] = 0.f;
        }
    } else if (blk < PREP_ACT) {
        const int bb = blk - PREP_E1;
        const uint4 z = make_uint4(0, 0, 0, 0);
        for (int pl = 0; pl < 2; pl++) {
            __nv_bfloat16* A = pl ? d_act_lo : d_act_hi;
            uint4* r0 = (uint4*)(A + ((long)bb * AR + 0) * AW * C2);
            uint4* r1 = (uint4*)(A + ((long)bb * AR + 129) * AW * C2);
            for (int i = t; i < AW * C2 / 8; i += 256) { r0[i] = z; r1[i] = z; }
            for (int i = t; i < 128 * 2 * 16; i += 256) {
                const int py  = 1 + (i >> 5);
                const int rem = i & 31;
                const int px  = (rem & 16) ? 129 : 0;
                const int ch  = rem & 15;
                *((uint4*)(A + (((long)bb * AR + py) * AW + px) * C2) + ch) = z;
            }
        }
    } else if (blk < PREP_W) {
        // head1 weight split: d_w1{h,l}[e][s][oc][ic]
        const int ws = blk - PREP_ACT;
        const int e  = ws / 9;
        const int s  = ws - e * 9;
        __nv_bfloat16* WH = d_w1h + (long)ws * (C2 * C2);
        __nv_bfloat16* WL = d_w1l + (long)ws * (C2 * C2);
        for (int i = t; i < C2 * C2; i += 256) {
            const int oc = i >> 7, ic = i & 127;
            const float w = e_hw1[(((long)e * C2 + oc) * C2 + ic) * 9 + s];
            const __nv_bfloat16 h = __float2bfloat16(w);
            WH[i] = h;
            WL[i] = __float2bfloat16(w - __bfloat162float(h));
        }
    } else {
        // conv1 weight split: d_w1c[slot][ky][kx*64+oc][ch16]
        // slots 0..NE*7-1: experts; slots NE*7..NE*7+6: gating
        const int ws = blk - PREP_W;           // 0..(NE+1)*7-1
        const int e  = ws / 7;                 // e==NE -> gating
        const int ky = ws - e * 7;
        __nv_bfloat16* WH = d_w1c_h + (long)ws * (7 * C1 * 16);
        __nv_bfloat16* WL = d_w1c_l + (long)ws * (7 * C1 * 16);
        const float* src = (e < NE) ? (e_conv1 + (long)e * C1 * CIN * 49)
                                    : g_conv_w;
        for (int i = t; i < 7 * C1 * 16; i += 256) {
            const int kx = i >> 10;
            const int rem = i & 1023;
            const int oc = rem >> 4, ch = rem & 15;
            float w = 0.f;
            if (ch < CIN)
                w = src[(((long)oc * CIN + ch) * 49) + ky * 7 + kx];
            const __nv_bfloat16 h = __float2bfloat16(w);
            WH[i] = h;
            WL[i] = __float2bfloat16(w - __bfloat162float(h));
        }
    }
}

// ---------------------------------------------------------------------------
// Kernel 1: 7x7 s2 conv (15->64) via mma.sync + ldmatrix bf16x2.
// GATING=true : weight slot NE, BN affine + ReLU -> d_gbuf (plain layout);
//               must NOT read d_eidx (runs before gate selection).
// GATING=false: weight slot d_eidx[b], ReLU -> d_ebuf1p (deinterleaved fp32).
// Grid (256 rows, 2 px-halves, 8 b), 256 thr = 8 warps (4 px-tiles x 2 oc-32).
// ---------------------------------------------------------------------------
#define C1P      48                      // smem pitch (bytes)
#define A_EV     0
#define A_OD     (132*C1P)
#define A_PL     (264*C1P)               // 12672 B per precision plane
#define B_OF     (2*A_PL)
#define B_PL     (448*C1P)               // 21504 B
#define CONV1_SMEM (2*A_PL + 2*B_PL)     // 68352 B

template <bool GATING>
__global__ void __launch_bounds__(256)
conv1_mma_kernel(const float* __restrict__ bn_gamma,
                 const float* __restrict__ bn_beta,
                 const float* __restrict__ bn_mean,
                 const float* __restrict__ bn_var)
{
    extern __shared__ __align__(16) char sm[];
    const int oy   = blockIdx.x;          // output row 0..255
    const int xh   = blockIdx.y;          // px half
    const int b    = blockIdx.z;
    const int t    = threadIdx.x;
    const int wid  = t >> 5;
    const int lane = t & 31;
    const int g    = lane >> 2;
    const int tg   = lane & 3;
    const int slot = GATING ? NE : d_eidx[b];
    const int pxbase = xh * 128;
    const int px0  = (wid & 3) * 32;
    const int och  = (wid >> 2) * 32;

    const uint32_t smb   = smem_u32(sm);
    const uint32_t aLane = (uint32_t)(lane & 15) * C1P + ((lane >> 4) * 16);
    const uint32_t bLane = (uint32_t)(lane & 7) * C1P + (((lane >> 3) & 1) * 16);

    float acc[2][4][4];
#pragma unroll
    for (int mt = 0; mt < 2; mt++)
#pragma unroll
        for (int nt = 0; nt < 4; nt++)
#pragma unroll
            for (int j = 0; j < 4; j++) acc[mt][nt][j] = 0.f;

#pragma unroll 1
    for (int ky = 0; ky < 7; ky++) {
        const int row = 2 * oy + ky;
        const __nv_bfloat16* sH = d_xnh_h + (long)(b * 520 + row) * (XNW * 16);
        const __nv_bfloat16* sL = d_xnh_l + (long)(b * 520 + row) * (XNW * 16);
        const uint4* eH = (const uint4*)(sH + (long)pxbase * 16);
        const uint4* eL = (const uint4*)(sL + (long)pxbase * 16);
        const uint4* oH = (const uint4*)(sH + (long)(pxbase + 260) * 16);
        const uint4* oL = (const uint4*)(sL + (long)(pxbase + 260) * 16);
        const uint4* wH = (const uint4*)(d_w1c_h + (long)(slot * 7 + ky) * (7 * C1 * 16));
        const uint4* wL = (const uint4*)(d_w1c_l + (long)(slot * 7 + ky) * (7 * C1 * 16));

        if (ky) __syncthreads();
        for (int i = t; i < 260; i += 256) {
            const int d0 = A_EV + (i >> 1) * C1P + ((i & 1) << 4);
            *(uint4*)(sm + d0)        = eH[i];
            *(uint4*)(sm + A_PL + d0) = eL[i];
        }
        for (int i = t; i < 262; i += 256) {
            const int d0 = A_OD + (i >> 1) * C1P + ((i & 1) << 4);
            *(uint4*)(sm + d0)        = oH[i];
            *(uint4*)(sm + A_PL + d0) = oL[i];
        }
        for (int i = t; i < 896; i += 256) {
            const int d0 = B_OF + (i >> 1) * C1P + ((i & 1) << 4);
            *(uint4*)(sm + d0)        = wH[i];
            *(uint4*)(sm + B_PL + d0) = wL[i];
        }
        __syncthreads();

#pragma unroll 1
        for (int kx = 0; kx < 7; kx++) {
            const uint32_t aoff = (kx & 1)
                ? (uint32_t)(A_EV + ((kx - 1) >> 1) * C1P)
                : (uint32_t)(A_OD + (kx >> 1) * C1P);
            const uint32_t aH0 = smb + aoff + (uint32_t)px0 * C1P + aLane;
            uint32_t AH[2][4], AL[2][4];
#pragma unroll
            for (int mt = 0; mt < 2; mt++) {
                ldm_x4(AH[mt], aH0 + (uint32_t)(mt * 16 * C1P));
                ldm_x4(AL[mt], aH0 + (uint32_t)(mt * 16 * C1P) + A_PL);
            }
#pragma unroll
            for (int nt = 0; nt < 4; nt++) {
                const uint32_t bAddr = smb + B_OF
                    + (uint32_t)(kx * 64 + och + nt * 8) * C1P + bLane;
                uint32_t BH0, BH1, BL0, BL1;
                ldm_x2(BH0, BH1, bAddr);
                ldm_x2(BL0, BL1, bAddr + B_PL);
#pragma unroll
                for (int mt = 0; mt < 2; mt++) {
                    mma_bf16(acc[mt][nt], AH[mt][0], AH[mt][1], AH[mt][2], AH[mt][3], BH0, BH1);
                    mma_bf16(acc[mt][nt], AH[mt][0], AH[mt][1], AH[mt][2], AH[mt][3], BL0, BL1);
                    mma_bf16(acc[mt][nt], AL[mt][0], AL[mt][1], AL[mt][2], AL[mt][3], BH0, BH1);
                }
            }
        }
    }

    if (GATING) {
        // BN affine + ReLU -> gbuf plain [b][oc][oy][px]
#pragma unroll
        for (int nt = 0; nt < 4; nt++) {
            const int oc0 = och + nt * 8 + 2 * tg;
            const int oc1 = oc0 + 1;
            const float s0 = bn_gamma[oc0] * rsqrtf(bn_var[oc0] + 1e-5f);
            const float s1 = bn_gamma[oc1] * rsqrtf(bn_var[oc1] + 1e-5f);
            const float t0 = bn_beta[oc0] - bn_mean[oc0] * s0;
            const float t1 = bn_beta[oc1] - bn_mean[oc1] * s1;
            float* b0 = d_gbuf + ((long)(b * C1 + oc0) * H1 + oy) * W1;
            float* b1 = d_gbuf + ((long)(b * C1 + oc1) * H1 + oy) * W1;
#pragma unroll
            for (int mt = 0; mt < 2; mt++) {
                const int px = pxbase + px0 + mt * 16 + g;
                b0[px]     = fmaxf(acc[mt][nt][0] * s0 + t0, 0.f);
                b1[px]     = fmaxf(acc[mt][nt][1] * s1 + t1, 0.f);
                b0[px + 8] = fmaxf(acc[mt][nt][2] * s0 + t0, 0.f);
                b1[px + 8] = fmaxf(acc[mt][nt][3] * s1 + t1, 0.f);
            }
        }
    } else {
        // ReLU -> ebuf1p deinterleaved fp32 (parity = g&1)
#pragma unroll
        for (int nt = 0; nt < 4; nt++) {
            const int oc0 = och + nt * 8 + 2 * tg;
            float* b0 = d_ebuf1p + ((long)(b * C1 + oc0) * E1R + (oy + 1)) * E1W;
            float* b1 = d_ebuf1p + ((long)(b * C1 + oc0 + 1) * E1R + (oy + 1)) * E1W;
#pragma unroll
            for (int mt = 0; mt < 2; mt++) {
                const int px = pxbase + px0 + mt * 16 + g;
                const int pos = (g & 1) ? (129 + (px >> 1)) : (px >> 1);
                b0[pos]     = fmaxf(acc[mt][nt][0], 0.f);
                b1[pos]     = fmaxf(acc[mt][nt][1], 0.f);
                b0[pos + 4] = fmaxf(acc[mt][nt][2], 0.f);
                b1[pos + 4] = fmaxf(acc[mt][nt][3], 0.f);
            }
        }
    }
}

// ---------------------------------------------------------------------------
// Kernel 2: maxpool 3x3 s2 pad1 + spatial mean, per (b,c).
// ---------------------------------------------------------------------------
__global__ void pool_mean_kernel()
{
    const int bc = blockIdx.x;
    const float* p = d_gbuf + (long)bc * (H1 * W1);
    float sum = 0.f;
    for (int i = threadIdx.x; i < H2 * W2; i += blockDim.x) {
        const int py = i >> 7, px = i & 127;
        float m = -1e30f;
#pragma unroll
        for (int dy = 0; dy < 3; dy++) {
            const int iy = py * 2 - 1 + dy;
            if ((unsigned)iy >= (unsigned)H1) continue;
            const float* row = p + iy * W1;
#pragma unroll
            for (int dx = 0; dx < 3; dx++) {
                const int ix = px * 2 - 1 + dx;
                if ((unsigned)ix < (unsigned)W1) m = fmaxf(m, row[ix]);
            }
        }
        sum += m;
    }
    __shared__ float red[256];
    red[threadIdx.x] = sum;
    __syncthreads();
    for (int s = 128; s > 0; s >>= 1) {
        if (threadIdx.x < s) red[threadIdx.x] += red[threadIdx.x + s];
        __syncthreads();
    }
    if (threadIdx.x == 0) d_pooled[bc] = red[0] * (1.f / (H2 * W2));
}

// ---------------------------------------------------------------------------
// Kernel 3: FC -> logits -> top-1 expert + aux loss.
// ---------------------------------------------------------------------------
__global__ void gate_finalize_kernel(const float* __restrict__ fcw,
                                     const float* __restrict__ fcb,
                                     float* __restrict__ out_loss)
{
    __shared__ float logits[B][NE];
    const int t = threadIdx.x;
    if (t < B * NE) {
        const int b = t / NE, e = t % NE;
        float s = fcb[e];
        const float* pw = fcw + e * C1;
        const float* pp = d_pooled + b * C1;
        for (int i = 0; i < C1; i++) s += pp[i] * pw[i];
        logits[b][e] = s;
    }
    __syncthreads();
    if (t == 0) {
        float dens[NE]  = {0.f, 0.f, 0.f};
        float proxy[NE] = {0.f, 0.f, 0.f};
        for (int b = 0; b < B; b++) {
            int bi = 0;
            for (int e = 1; e < NE; e++)
                if (logits[b][e] > logits[b][bi]) bi = e;
            d_eidx[b] = bi;
            dens[bi] += 1.f / B;
            float mx = logits[b][0];
            for (int e = 1; e < NE; e++) mx = fmaxf(mx, logits[b][e]);
            float ex[NE], sum = 0.f;
            for (int e = 0; e < NE; e++) { ex[e] = expf(logits[b][e] - mx); sum += ex[e]; }
            for (int e = 0; e < NE; e++) proxy[e] += ex[e] / sum * (1.f / B);
        }
        float aux = 0.f;
        for (int e = 0; e < NE; e++) aux += dens[e] * proxy[e];
        *out_loss = 0.01f * aux * (float)NE;
    }
}

// ---------------------------------------------------------------------------
// Kernel 4: 3x3 s2 conv, 64 -> 128.  Epilogue writes NHWC bf16x2.
// ---------------------------------------------------------------------------
__global__ void __launch_bounds__(128, 4)
conv2_kernel(const float* __restrict__ w_all)
{
    const int oy  = blockIdx.x * 8 + (threadIdx.x >> 4);
    const int ocg = blockIdx.y;
    const int b   = blockIdx.z;
    const int l   = threadIdx.x & 15;

    const float* w = w_all + ((long)d_eidx[b] * C2 + ocg * 8) * CONV2_K;
    __shared__ __align__(16) float wsm[CONV2_K][8];
    for (int idx = threadIdx.x; idx < 8 * CONV2_K; idx += 128) {
        const int o = idx / CONV2_K;
        const int k = idx - o * CONV2_K;
        wsm[k][o] = w[idx];
    }
    __syncthreads();

    unsigned long long acc[8][4];
#pragma unroll
    for (int p = 0; p < 8; p++)
#pragma unroll
        for (int j = 0; j < 4; j++) acc[p][j] = 0ull;

    const float* ib = d_ebuf1p + (long)b * C1 * (E1R * E1W);
#pragma unroll 1
    for (int ic = 0; ic < C1; ic++) {
        const float* xc = ib + (long)ic * (E1R * E1W);
#pragma unroll
        for (int ky = 0; ky < 3; ky++) {
            const float* row = xc + (2 * oy + ky) * E1W;
            const float4 e0 = *(const float4*)(row + 8 * l);
            const float4 e1 = *(const float4*)(row + 8 * l + 4);
            const float4 q0 = *(const float4*)(row + 128 + 8 * l);
            const float4 q1 = *(const float4*)(row + 128 + 8 * l + 4);
            const float4 q2 = *(const float4*)(row + 128 + 8 * l + 8);
            const float E[8]  = {e0.x, e0.y, e0.z, e0.w, e1.x, e1.y, e1.z, e1.w};
            const float O[12] = {q0.x, q0.y, q0.z, q0.w, q1.x, q1.y, q1.z, q1.w,
                                 q2.x, q2.y, q2.z, q2.w};
            const int kb = (ic * 3 + ky) * 3;
#pragma unroll
            for (int kx = 0; kx < 3; kx++) {
                const ulonglong2* wp = (const ulonglong2*)wsm[kb + kx];
                const ulonglong2 wA = wp[0], wB = wp[1];
#pragma unroll
                for (int p = 0; p < 8; p++) {
                    const float v = (kx == 1) ? E[p] : ((kx == 0) ? O[p] : O[p + 1]);
                    const unsigned long long vv = pack2(v);
                    FFMA2_8(acc[p], vv, wA, wB);
                }
            }
        }
    }

#pragma unroll
    for (int p = 0; p < 8; p++) {
        __align__(16) __nv_bfloat16 hi8[8];
        __align__(16) __nv_bfloat16 lo8[8];
#pragma unroll
        for (int j = 0; j < 4; j++) {
            const float va = fmaxf(f2lo(acc[p][j]), 0.f);
            const float vb = fmaxf(f2hi(acc[p][j]), 0.f);
            const __nv_bfloat16 ha = __float2bfloat16(va);
            const __nv_bfloat16 hb = __float2bfloat16(vb);
            hi8[2 * j]     = ha;
            lo8[2 * j]     = __float2bfloat16(va - __bfloat162float(ha));
            hi8[2 * j + 1] = hb;
            lo8[2 * j + 1] = __float2bfloat16(vb - __bfloat162float(hb));
        }
        const long off = (((long)b * AR + (oy + 1)) * AW + (8 * l + p + 1)) * C2
                       + ocg * 8;
        *(uint4*)(d_act_hi + off) = *(const uint4*)hi8;
        *(uint4*)(d_act_lo + off) = *(const uint4*)lo8;
    }
}

// ---------------------------------------------------------------------------
// Kernel 5: head1 via mma.sync bf16x2 + smem staging + ldmatrix (proven)
// ---------------------------------------------------------------------------
#define PITCHB   272
#define TILE_B   (128 * PITCHB)
#define OFF_AH   0
#define OFF_AL   TILE_B
#define OFF_BH   (2 * TILE_B)
#define OFF_BL   (3 * TILE_B)
#define HEAD1_SMEM (4 * TILE_B)

__global__ void __launch_bounds__(256)
head1_mma_kernel(const float* __restrict__ b_all)
{
    extern __shared__ __align__(16) char sm[];
    const int oy   = blockIdx.x;
    const int b    = blockIdx.y;
    const int t    = threadIdx.x;
    const int wid  = t >> 5;
    const int lane = t & 31;
    const int g    = lane >> 2;
    const int tg   = lane & 3;
    const int e    = d_eidx[b];
    const int px0  = (wid & 3) * 32;
    const int ocq  = (wid >> 2) * 64;

    const uint32_t smb = smem_u32(sm);
    const uint32_t aRow = (uint32_t)(px0 + (lane & 15)) * PITCHB + ((lane >> 4) * 16);
    const uint32_t bRow = (uint32_t)(ocq + (lane & 7)) * PITCHB + (((lane >> 3) & 1) * 16);
    const uint32_t aAH0 = smb + OFF_AH + aRow;
    const uint32_t aAL0 = smb + OFF_AL + aRow;
    const uint32_t aBH0 = smb + OFF_BH + bRow;
    const uint32_t aBL0 = smb + OFF_BL + bRow;

    float acc[2][8][4];
#pragma unroll
    for (int mt = 0; mt < 2; mt++)
#pragma unroll
        for (int nt = 0; nt < 8; nt++)
#pragma unroll
            for (int j = 0; j < 4; j++) acc[mt][nt][j] = 0.f;

#pragma unroll 1
    for (int s = 0; s < 9; s++) {
        const int dy = s / 3, dx = s - 3 * dy;
        const uint4* srcAH = (const uint4*)(d_act_hi + (((long)b * AR + (oy + dy)) * AW + dx) * C2);
        const uint4* srcAL = (const uint4*)(d_act_lo + (((long)b * AR + (oy + dy)) * AW + dx) * C2);
        const uint4* srcBH = (const uint4*)(d_w1h + (long)(e * 9 + s) * (C2 * C2));
        const uint4* srcBL = (const uint4*)(d_w1l + (long)(e * 9 + s) * (C2 * C2));

        if (s) __syncthreads();
#pragma unroll 1
        for (int idx = t; idx < 2048; idx += 256) {
            const int row = idx >> 4, ch = idx & 15;
            const int d0  = row * PITCHB + (ch << 4);
            *(uint4*)(sm + OFF_AH + d0) = srcAH[idx];
            *(uint4*)(sm + OFF_AL + d0) = srcAL[idx];
            *(uint4*)(sm + OFF_BH + d0) = srcBH[idx];
            *(uint4*)(sm + OFF_BL + d0) = srcBL[idx];
        }
        __syncthreads();

#pragma unroll 1
        for (int ks = 0; ks < 8; ks++) {
            const uint32_t ko = (uint32_t)(32 * ks);
            uint32_t AH[2][4], AL[2][4];
#pragma unroll
            for (int mt = 0; mt < 2; mt++) {
                ldm_x4(AH[mt], aAH0 + ko + (uint32_t)(mt * 16 * PITCHB));
                ldm_x4(AL[mt], aAL0 + ko + (uint32_t)(mt * 16 * PITCHB));
            }
#pragma unroll
            for (int nt = 0; nt < 8; nt++) {
                uint32_t BH0, BH1, BL0, BL1;
                ldm_x2(BH0, BH1, aBH0 + ko + (uint32_t)(nt * 8 * PITCHB));
                ldm_x2(BL0, BL1, aBL0 + ko + (uint32_t)(nt * 8 * PITCHB));
#pragma unroll
                for (int mt = 0; mt < 2; mt++) {
                    mma_bf16(acc[mt][nt], AH[mt][0], AH[mt][1], AH[mt][2], AH[mt][3], BH0, BH1);
                    mma_bf16(acc[mt][nt], AH[mt][0], AH[mt][1], AH[mt][2], AH[mt][3], BL0, BL1);
                    mma_bf16(acc[mt][nt], AL[mt][0], AL[mt][1], AL[mt][2], AL[mt][3], BH0, BH1);
                }
            }
        }
    }

#pragma unroll
    for (int nt = 0; nt < 8; nt++) {
        const int oc0 = ocq + nt * 8 + 2 * tg;
        const float bias0 = b_all[e * C2 + oc0];
        const float bias1 = b_all[e * C2 + oc0 + 1];
        float* o0 = d_ebuf3 + ((long)(b * C2 + oc0) * H2 + oy) * W2;
        float* o1 = d_ebuf3 + ((long)(b * C2 + oc0 + 1) * H2 + oy) * W2;
#pragma unroll
        for (int mt = 0; mt < 2; mt++) {
            const int px = px0 + mt * 16 + g;
            o0[px]     = fmaxf(acc[mt][nt][0] + bias0, 0.f);
            o1[px]     = fmaxf(acc[mt][nt][1] + bias1, 0.f);
            o0[px + 8] = fmaxf(acc[mt][nt][2] + bias0, 0.f);
            o1[px + 8] = fmaxf(acc[mt][nt][3] + bias1, 0.f);
        }
    }
}

// ---------------------------------------------------------------------------
// Kernel 6: 1x1 conv 128 -> 5 + bias, scatter into (hm, wh, reg) layout.
// ---------------------------------------------------------------------------
__global__ void __launch_bounds__(128)
head2_kernel(const float* __restrict__ w_all,
             const float* __restrict__ b_all,
             float* __restrict__ out)
{
    const int oy = blockIdx.x;
    const int b  = blockIdx.y;
    const int ox = threadIdx.x;
    const int e  = d_eidx[b];

    __shared__ __align__(16) float ws[C2][8];
    for (int idx = threadIdx.x; idx < 5 * C2; idx += 128) {
        const int j = idx / C2, ic = idx - j * C2;
        ws[ic][j] = w_all[(long)e * 5 * C2 + idx];
    }
    __syncthreads();

    float acc[5] = {0.f, 0.f, 0.f, 0.f, 0.f};
    const float* ib = d_ebuf3 + (long)b * C2 * H2 * W2 + oy * W2 + ox;
    for (int ic = 0; ic < C2; ic++) {
        const float v = __ldg(ib + ic * (H2 * W2));
        const float4 w4 = *(const float4*)ws[ic];
        acc[0] += v * w4.x;
        acc[1] += v * w4.y;
        acc[2] += v * w4.z;
        acc[3] += v * w4.w;
        acc[4] += v * ws[ic][4];
    }

    const int p  = oy * W2 + ox;
    const int HW = H2 * W2;
    const float* bb = b_all + e * 5;
    out[b * HW + p]                        = acc[0] + bb[0];
    out[B * HW + (b * 2 + 0) * HW + p]     = acc[1] + bb[1];
    out[B * HW + (b * 2 + 1) * HW + p]     = acc[2] + bb[2];
    out[3 * B * HW + (b * 2 + 0) * HW + p] = acc[3] + bb[3];
    out[3 * B * HW + (b * 2 + 1) * HW + p] = acc[4] + bb[4];
}

// ---------------------------------------------------------------------------
// Launch
// ---------------------------------------------------------------------------
extern "C" void kernel_launch(void* const* d_in, const int* in_sizes, int n_in,
                              void* d_out, int out_size)
{
    const float* x        = (const float*)d_in[0];
    const float* g_conv_w = (const float*)d_in[1];
    const float* g_gamma  = (const float*)d_in[2];
    const float* g_beta   = (const float*)d_in[3];
    const float* g_mean   = (const float*)d_in[4];
    const float* g_var    = (const float*)d_in[5];
    const float* g_fc_w   = (const float*)d_in[6];
    const float* g_fc_b   = (const float*)d_in[7];
    const float* e_conv1  = (const float*)d_in[8];
    const float* e_conv2  = (const float*)d_in[9];
    const float* e_hw1    = (const float*)d_in[10];
    const float* e_hb1    = (const float*)d_in[11];
    const float* e_hw2    = (const float*)d_in[12];
    const float* e_hb2    = (const float*)d_in[13];
    float* out = (float*)d_out;

    cudaFuncSetAttribute(head1_mma_kernel,
                         cudaFuncAttributeMaxDynamicSharedMemorySize,
                         HEAD1_SMEM);
    cudaFuncSetAttribute(conv1_mma_kernel<true>,
                         cudaFuncAttributeMaxDynamicSharedMemorySize,
                         CONV1_SMEM);
    cudaFuncSetAttribute(conv1_mma_kernel<false>,
                         cudaFuncAttributeMaxDynamicSharedMemorySize,
                         CONV1_SMEM);

    // 0. Layout prep (NHWC-16 input, halos, weight splits incl. gating)
    prep_kernel<<<PREP_W1, 256>>>(x, e_hw1, e_conv1, g_conv_w);
    // 1. Gating conv (7x7 s2) via mma.sync bf16x2 + BN + ReLU -> gbuf
    conv1_mma_kernel<true><<<dim3(256, 2, B), 256, CONV1_SMEM>>>(g_gamma, g_beta, g_mean, g_var);
    // 2. Maxpool + global average
    pool_mean_kernel<<<B * C1, 256>>>();
    // 3. Logits, top-1 expert selection, aux loss
    gate_finalize_kernel<<<1, 32>>>(g_fc_w, g_fc_b, out + (out_size - 1));
    // 4. Expert conv1 (7x7 s2) via mma.sync bf16x2 -> ebuf1p fp32
    conv1_mma_kernel<false><<<dim3(256, 2, B), 256, CONV1_SMEM>>>(nullptr, nullptr, nullptr, nullptr);
    // 5. Expert conv2 (3x3 s2) + ReLU -> NHWC bf16x2
    conv2_kernel<<<dim3(16, 16, B), 128>>>(e_conv2);
    // 6. Head conv1 via mma.sync + ldmatrix bf16x2 -> ebuf3
    head1_mma_kernel<<<dim3(H2, B), 256, HEAD1_SMEM>>>(e_hb1);
    // 7. Head conv2 (1x1) + bias, scattered to (hm, wh, reg)
    head2_kernel<<<dim3(128, B), 128>>>(e_hw2, e_hb2, out);
}